// round 4
// baseline (speedup 1.0000x reference)
#include <cuda_runtime.h>

#define TOK   8192   // L*N tokens
#define EDIM  256
#define HD    32
#define NB    8      // batch N
#define LQ    1024   // seq len

// Scratch: 6 projection buffers (Q,K,V,Qt,Kt,Vt) + 2 attention outputs
__device__ float g_proj[6][TOK * EDIM];
__device__ float g_att[2][TOK * EDIM];

// ---------------------------------------------------------------------------
// GEMM: C[M,256] = X[M,256] @ W[256,256]^T + bias   (torch Linear)
// Tile 128x64, BK=32, 256 threads, 8x4 micro-tile.
// ---------------------------------------------------------------------------
__device__ __forceinline__ void gemm_nt_128x64(
    const float* __restrict__ X, const float* __restrict__ W,
    const float* __restrict__ bias, float* __restrict__ C)
{
    __shared__ float Xs[32][128];
    __shared__ float Ws[32][64];
    const int tid = threadIdx.x;
    const int tx = tid & 15;          // 16 col-groups of 4
    const int ty = tid >> 4;          // 16 row-groups of 8
    const int m0 = blockIdx.y * 128;
    const int n0 = blockIdx.x * 64;

    float acc[8][4];
#pragma unroll
    for (int i = 0; i < 8; i++)
#pragma unroll
        for (int j = 0; j < 4; j++) acc[i][j] = 0.f;

    for (int k0 = 0; k0 < EDIM; k0 += 32) {
        // X tile: 128 rows x 32 k  (1024 float4, 4 per thread)
#pragma unroll
        for (int i = 0; i < 4; i++) {
            int id  = tid + i * 256;
            int row = id >> 3;
            int c4  = (id & 7) * 4;
            float4 vv = *(const float4*)&X[(m0 + row) * EDIM + k0 + c4];
            Xs[c4 + 0][row] = vv.x; Xs[c4 + 1][row] = vv.y;
            Xs[c4 + 2][row] = vv.z; Xs[c4 + 3][row] = vv.w;
        }
        // W tile: 64 rows x 32 k (512 float4, 2 per thread)
#pragma unroll
        for (int i = 0; i < 2; i++) {
            int id  = tid + i * 256;
            int row = id >> 3;
            int c4  = (id & 7) * 4;
            float4 vv = *(const float4*)&W[(n0 + row) * EDIM + k0 + c4];
            Ws[c4 + 0][row] = vv.x; Ws[c4 + 1][row] = vv.y;
            Ws[c4 + 2][row] = vv.z; Ws[c4 + 3][row] = vv.w;
        }
        __syncthreads();
#pragma unroll
        for (int kk = 0; kk < 32; kk++) {
            float4 a0 = *(const float4*)&Xs[kk][ty * 8];
            float4 a1 = *(const float4*)&Xs[kk][ty * 8 + 4];
            float4 b  = *(const float4*)&Ws[kk][tx * 4];
            float av[8] = {a0.x, a0.y, a0.z, a0.w, a1.x, a1.y, a1.z, a1.w};
            float bv[4] = {b.x, b.y, b.z, b.w};
#pragma unroll
            for (int i = 0; i < 8; i++)
#pragma unroll
                for (int j = 0; j < 4; j++)
                    acc[i][j] = fmaf(av[i], bv[j], acc[i][j]);
        }
        __syncthreads();
    }

    float4 bb = *(const float4*)&bias[n0 + tx * 4];
#pragma unroll
    for (int i = 0; i < 8; i++) {
        float4 o;
        o.x = acc[i][0] + bb.x; o.y = acc[i][1] + bb.y;
        o.z = acc[i][2] + bb.z; o.w = acc[i][3] + bb.w;
        *(float4*)&C[(size_t)(m0 + ty * 8 + i) * EDIM + n0 + tx * 4] = o;
    }
}

__global__ __launch_bounds__(256) void inproj_kernel(
    const float* q,  const float* k,  const float* v,
    const float* qt, const float* kt, const float* vt,
    const float* wq, const float* wk, const float* wv,
    const float* bq, const float* bk, const float* bv,
    const float* wqt, const float* wkt, const float* wvt,
    const float* bqt, const float* bkt, const float* bvt)
{
    const float* Xp[6] = {q, k, v, qt, kt, vt};
    const float* Wp[6] = {wq, wk, wv, wqt, wkt, wvt};
    const float* Bp[6] = {bq, bk, bv, bqt, bkt, bvt};
    const int z = blockIdx.z;
    gemm_nt_128x64(Xp[z], Wp[z], Bp[z], g_proj[z]);
}

__global__ __launch_bounds__(256) void outproj_kernel(
    const float* wo, const float* bo,
    const float* wot, const float* bot, float* out)
{
    const int z = blockIdx.z;
    gemm_nt_128x64(g_att[z], z ? wot : wo, z ? bot : bo,
                   out + (size_t)z * TOK * EDIM);
}

// ---------------------------------------------------------------------------
// Flash attention, fp32. 1 thread = 1 query row; 128 rows/CTA.
// blockIdx.y encodes (stream, n, h); blockIdx.x = query block.
// ---------------------------------------------------------------------------
__global__ __launch_bounds__(128) void attn_kernel()
{
    const int tid    = threadIdx.x;
    const int idx    = blockIdx.y;
    const int stream = idx >> 6;
    const int n      = (idx >> 3) & 7;
    const int h      = idx & 7;

    const float* __restrict__ Qb = g_proj[stream * 3 + 0];
    const float* __restrict__ Kb = g_proj[stream * 3 + 1];
    const float* __restrict__ Vb = g_proj[stream * 3 + 2];
    float* __restrict__ Ob = g_att[stream];

    const int l    = blockIdx.x * 128 + tid;
    const int base = (l * NB + n) * EDIM + h * HD;

    const float scale = 0.17677669529663687f;   // 1/sqrt(32)
    float q[32], O[32];
#pragma unroll
    for (int c = 0; c < 8; c++) {
        float4 vv = *(const float4*)&Qb[base + c * 4];
        q[c * 4 + 0] = vv.x * scale; q[c * 4 + 1] = vv.y * scale;
        q[c * 4 + 2] = vv.z * scale; q[c * 4 + 3] = vv.w * scale;
    }
#pragma unroll
    for (int d = 0; d < 32; d++) O[d] = 0.f;
    float m = -1e30f, lsum = 0.f;

    __shared__ float4 Ks[64][8];
    __shared__ float4 Vs[64][8];

    for (int s0 = 0; s0 < LQ; s0 += 64) {
        // stage 64 K rows + 64 V rows (hd=32): 512 float4 each, 4 per thread
#pragma unroll
        for (int i = 0; i < 4; i++) {
            int id  = tid + i * 128;
            int row = id >> 3;
            int c4  = id & 7;
            int off = ((s0 + row) * NB + n) * EDIM + h * HD + c4 * 4;
            Ks[row][c4] = *(const float4*)&Kb[off];
            Vs[row][c4] = *(const float4*)&Vb[off];
        }
        __syncthreads();

#pragma unroll
        for (int half = 0; half < 2; half++) {
            float sc[32];
            float cmax = -1e30f;
#pragma unroll
            for (int j = 0; j < 32; j++) {
                int jj = half * 32 + j;
                float p0 = 0.f, p1 = 0.f, p2 = 0.f, p3 = 0.f;
#pragma unroll
                for (int c = 0; c < 8; c++) {
                    float4 kv = Ks[jj][c];
                    p0 = fmaf(q[c * 4 + 0], kv.x, p0);
                    p1 = fmaf(q[c * 4 + 1], kv.y, p1);
                    p2 = fmaf(q[c * 4 + 2], kv.z, p2);
                    p3 = fmaf(q[c * 4 + 3], kv.w, p3);
                }
                float s = (p0 + p1) + (p2 + p3);
                sc[j] = s;
                cmax = fmaxf(cmax, s);
            }

            float mnew = fmaxf(m, cmax);
            float corr = __expf(m - mnew);
            lsum *= corr;
#pragma unroll
            for (int d = 0; d < 32; d++) O[d] *= corr;

#pragma unroll
            for (int j = 0; j < 32; j++) {
                int jj = half * 32 + j;
                float p = __expf(sc[j] - mnew);
                lsum += p;
#pragma unroll
                for (int c = 0; c < 8; c++) {
                    float4 vv = Vs[jj][c];
                    O[c * 4 + 0] = fmaf(p, vv.x, O[c * 4 + 0]);
                    O[c * 4 + 1] = fmaf(p, vv.y, O[c * 4 + 1]);
                    O[c * 4 + 2] = fmaf(p, vv.z, O[c * 4 + 2]);
                    O[c * 4 + 3] = fmaf(p, vv.w, O[c * 4 + 3]);
                }
            }
            m = mnew;
        }
        __syncthreads();
    }

    const float inv = 1.f / lsum;
#pragma unroll
    for (int c = 0; c < 8; c++) {
        float4 o;
        o.x = O[c * 4 + 0] * inv; o.y = O[c * 4 + 1] * inv;
        o.z = O[c * 4 + 2] * inv; o.w = O[c * 4 + 3] * inv;
        *(float4*)&Ob[base + c * 4] = o;
    }
}

// ---------------------------------------------------------------------------
// Input order = setup_inputs() dict order:
//  0 query, 1 key, 2 value, 3 query_teacher, 4 key_teacher, 5 value_teacher,
//  6 w_q, 7 w_k, 8 w_v, 9 w_q_teacher, 10 w_k_teacher, 11 w_v_teacher,
//  12 w_out, 13 w_out_teacher,
//  14 b_q, 15 b_k, 16 b_v, 17 b_q_teacher, 18 b_k_teacher, 19 b_v_teacher,
//  20 b_out, 21 b_out_teacher
// ---------------------------------------------------------------------------
extern "C" void kernel_launch(void* const* d_in, const int* in_sizes, int n_in,
                              void* d_out, int out_size)
{
    const float* P[22];
    for (int i = 0; i < 22; i++) P[i] = (const float*)d_in[i];

    dim3 gin(4, 64, 6);
    inproj_kernel<<<gin, 256>>>(
        P[0], P[1], P[2], P[3], P[4], P[5],        // activations
        P[6], P[7], P[8],                          // w_q, w_k, w_v
        P[14], P[15], P[16],                       // b_q, b_k, b_v
        P[9], P[10], P[11],                        // w_q_t, w_k_t, w_v_t
        P[17], P[18], P[19]);                      // b_q_t, b_k_t, b_v_t

    dim3 gat(8, 128);               // 8 query blocks x (2 streams * 8 n * 8 h)
    attn_kernel<<<gat, 128>>>();

    dim3 gout(4, 64, 2);
    outproj_kernel<<<gout, 256>>>(
        P[12], P[20],                              // w_out, b_out
        P[13], P[21],                              // w_out_teacher, b_out_teacher
        (float*)d_out);
}

// round 7
// speedup vs baseline: 1.4193x; 1.4193x over previous
#include <cuda_runtime.h>
#include <cuda_bf16.h>

#define TOK   8192   // L*N tokens
#define EDIM  256
#define HD    32
#define NB    8      // batch N
#define LQ    1024   // seq len
#define PADK  40     // bf16 elements per smem row (stride) — conflict-free frag loads

// Scratch: 6 projection buffers (Q,K,V,Qt,Kt,Vt) + 2 attention outputs
__device__ float g_proj[6][TOK * EDIM];
__device__ float g_att[2][TOK * EDIM];

// ---------------------------------------------------------------------------
// helpers
// ---------------------------------------------------------------------------
__device__ __forceinline__ void mma_bf16(float4& d,
    unsigned a0, unsigned a1, unsigned a2, unsigned a3,
    unsigned b0, unsigned b1)
{
    asm volatile(
        "mma.sync.aligned.m16n8k16.row.col.f32.bf16.bf16.f32 "
        "{%0,%1,%2,%3}, {%4,%5,%6,%7}, {%8,%9}, {%0,%1,%2,%3};"
        : "+f"(d.x), "+f"(d.y), "+f"(d.z), "+f"(d.w)
        : "r"(a0), "r"(a1), "r"(a2), "r"(a3), "r"(b0), "r"(b1));
}

// split 4 fp32 into bf16 hi + bf16 residual lo, store to smem planes
__device__ __forceinline__ void split_store4(
    __nv_bfloat16* hi, __nv_bfloat16* lo, int base, float4 v)
{
    __nv_bfloat162 h01 = __floats2bfloat162_rn(v.x, v.y);
    __nv_bfloat162 h23 = __floats2bfloat162_rn(v.z, v.w);
    float2 f01 = __bfloat1622float2(h01);
    float2 f23 = __bfloat1622float2(h23);
    __nv_bfloat162 l01 = __floats2bfloat162_rn(v.x - f01.x, v.y - f01.y);
    __nv_bfloat162 l23 = __floats2bfloat162_rn(v.z - f23.x, v.w - f23.y);
    *reinterpret_cast<__nv_bfloat162*>(&hi[base])     = h01;
    *reinterpret_cast<__nv_bfloat162*>(&hi[base + 2]) = h23;
    *reinterpret_cast<__nv_bfloat162*>(&lo[base])     = l01;
    *reinterpret_cast<__nv_bfloat162*>(&lo[base + 2]) = l23;
}

// split-pack 2 fp32 into packed bf16x2 hi and lo (for register-resident P)
__device__ __forceinline__ void split_pack2(float x, float y, unsigned& h, unsigned& l)
{
    __nv_bfloat162 hh = __floats2bfloat162_rn(x, y);
    float2 ff = __bfloat1622float2(hh);
    __nv_bfloat162 ll = __floats2bfloat162_rn(x - ff.x, y - ff.y);
    h = *reinterpret_cast<unsigned*>(&hh);
    l = *reinterpret_cast<unsigned*>(&ll);
}

__device__ __forceinline__ unsigned ldu(const __nv_bfloat16* p)
{
    return *reinterpret_cast<const unsigned*>(p);
}

// ---------------------------------------------------------------------------
// GEMM: C[M,256] = X[M,256] @ W[256,256]^T + bias, bf16x3 split MMA.
// CTA tile 128x128, 8 warps (4m x 2n), warp tile 32x64.
// ---------------------------------------------------------------------------
__device__ __forceinline__ void gemm_nt_mma(
    const float* __restrict__ X, const float* __restrict__ W,
    const float* __restrict__ bias, float* __restrict__ C)
{
    __shared__ __nv_bfloat16 Xh[128 * PADK], Xl[128 * PADK];
    __shared__ __nv_bfloat16 Wh[128 * PADK], Wl[128 * PADK];

    const int tid  = threadIdx.x;
    const int wid  = tid >> 5;
    const int lane = tid & 31;
    const int g = lane >> 2, t = lane & 3;
    const int wm = (wid >> 1) * 32;
    const int wn = (wid & 1) * 64;
    const int m0 = blockIdx.y * 128;
    const int n0 = blockIdx.x * 128;

    float4 acc[2][8];
#pragma unroll
    for (int i = 0; i < 2; i++)
#pragma unroll
        for (int j = 0; j < 8; j++) acc[i][j] = make_float4(0.f, 0.f, 0.f, 0.f);

    for (int k0 = 0; k0 < EDIM; k0 += 32) {
        // stage X tile [128][32] and W tile [128][32], split to hi/lo
#pragma unroll
        for (int i = 0; i < 4; i++) {
            int id  = tid + i * 256;
            int row = id >> 3;
            int c4  = (id & 7) * 4;
            float4 xv = *(const float4*)&X[(size_t)(m0 + row) * EDIM + k0 + c4];
            split_store4(Xh, Xl, row * PADK + c4, xv);
            float4 wv = *(const float4*)&W[(size_t)(n0 + row) * EDIM + k0 + c4];
            split_store4(Wh, Wl, row * PADK + c4, wv);
        }
        __syncthreads();

#pragma unroll
        for (int ks = 0; ks < 2; ks++) {
            const int kb = ks * 16 + 2 * t;
            unsigned ah[2][4], al[2][4];
#pragma unroll
            for (int mt = 0; mt < 2; mt++) {
                int r = wm + mt * 16 + g;
                ah[mt][0] = ldu(&Xh[r * PADK + kb]);
                ah[mt][1] = ldu(&Xh[(r + 8) * PADK + kb]);
                ah[mt][2] = ldu(&Xh[r * PADK + kb + 8]);
                ah[mt][3] = ldu(&Xh[(r + 8) * PADK + kb + 8]);
                al[mt][0] = ldu(&Xl[r * PADK + kb]);
                al[mt][1] = ldu(&Xl[(r + 8) * PADK + kb]);
                al[mt][2] = ldu(&Xl[r * PADK + kb + 8]);
                al[mt][3] = ldu(&Xl[(r + 8) * PADK + kb + 8]);
            }
#pragma unroll
            for (int nt = 0; nt < 8; nt++) {
                int c = wn + nt * 8 + g;
                unsigned bh0 = ldu(&Wh[c * PADK + kb]);
                unsigned bh1 = ldu(&Wh[c * PADK + kb + 8]);
                unsigned bl0 = ldu(&Wl[c * PADK + kb]);
                unsigned bl1 = ldu(&Wl[c * PADK + kb + 8]);
#pragma unroll
                for (int mt = 0; mt < 2; mt++) {
                    mma_bf16(acc[mt][nt], ah[mt][0], ah[mt][1], ah[mt][2], ah[mt][3], bh0, bh1);
                    mma_bf16(acc[mt][nt], ah[mt][0], ah[mt][1], ah[mt][2], ah[mt][3], bl0, bl1);
                    mma_bf16(acc[mt][nt], al[mt][0], al[mt][1], al[mt][2], al[mt][3], bh0, bh1);
                }
            }
        }
        __syncthreads();
    }

#pragma unroll
    for (int mt = 0; mt < 2; mt++)
#pragma unroll
        for (int nt = 0; nt < 8; nt++) {
            int row = m0 + wm + mt * 16 + g;
            int col = n0 + wn + nt * 8 + 2 * t;
            float2 bb = *(const float2*)&bias[col];
            float4 a = acc[mt][nt];
            float2 o0 = make_float2(a.x + bb.x, a.y + bb.y);
            float2 o1 = make_float2(a.z + bb.x, a.w + bb.y);
            *(float2*)&C[(size_t)row * EDIM + col] = o0;
            *(float2*)&C[(size_t)(row + 8) * EDIM + col] = o1;
        }
}

__global__ __launch_bounds__(256) void inproj_kernel(
    const float* q,  const float* k,  const float* v,
    const float* qt, const float* kt, const float* vt,
    const float* wq, const float* wk, const float* wv,
    const float* bq, const float* bk, const float* bv,
    const float* wqt, const float* wkt, const float* wvt,
    const float* bqt, const float* bkt, const float* bvt)
{
    const float* Xp[6] = {q, k, v, qt, kt, vt};
    const float* Wp[6] = {wq, wk, wv, wqt, wkt, wvt};
    const float* Bp[6] = {bq, bk, bv, bqt, bkt, bvt};
    const int z = blockIdx.z;
    gemm_nt_mma(Xp[z], Wp[z], Bp[z], g_proj[z]);
}

__global__ __launch_bounds__(256) void outproj_kernel(
    const float* wo, const float* bo,
    const float* wot, const float* bot, float* out)
{
    const int z = blockIdx.z;
    gemm_nt_mma(g_att[z], z ? wot : wo, z ? bot : bo,
                out + (size_t)z * TOK * EDIM);
}

// ---------------------------------------------------------------------------
// Flash attention, bf16x3 MMA, FA2-style register-resident P.
// CTA: 128 q rows, 8 warps (one m16 tile each), key chunks of 32.
// ---------------------------------------------------------------------------
__global__ __launch_bounds__(256) void attn_kernel()
{
    __shared__ __nv_bfloat16 Qh[128 * PADK], Ql[128 * PADK];
    __shared__ __nv_bfloat16 Kh[32 * PADK],  Kl[32 * PADK];
    __shared__ __nv_bfloat16 Vh[32 * PADK],  Vl[32 * PADK];  // transposed [hd][key]

    const int tid  = threadIdx.x;
    const int wid  = tid >> 5;
    const int lane = tid & 31;
    const int g = lane >> 2, t = lane & 3;

    const int idx    = blockIdx.y;
    const int stream = idx >> 6;
    const int n      = (idx >> 3) & 7;
    const int h      = idx & 7;

    const float* __restrict__ Qb = g_proj[stream * 3 + 0];
    const float* __restrict__ Kb = g_proj[stream * 3 + 1];
    const float* __restrict__ Vb = g_proj[stream * 3 + 2];
    float* __restrict__ Ob = g_att[stream];

    const int qbase = blockIdx.x * 128;
    const float scale = 0.17677669529663687f;   // 1/sqrt(32)

    // stage Q (scaled, split)
#pragma unroll
    for (int i = 0; i < 4; i++) {
        int id  = tid + i * 256;
        int row = id >> 3;
        int c4  = (id & 7) * 4;
        int off = ((qbase + row) * NB + n) * EDIM + h * HD + c4;
        float4 v = *(const float4*)&Qb[off];
        v.x *= scale; v.y *= scale; v.z *= scale; v.w *= scale;
        split_store4(Qh, Ql, row * PADK + c4, v);
    }
    __syncthreads();

    // per-warp Q fragments (persistent): 2 k-steps of k16
    unsigned qh[2][4], ql[2][4];
    const int ar = wid * 16;
#pragma unroll
    for (int ks = 0; ks < 2; ks++) {
        int kb = ks * 16 + 2 * t;
        qh[ks][0] = ldu(&Qh[(ar + g) * PADK + kb]);
        qh[ks][1] = ldu(&Qh[(ar + g + 8) * PADK + kb]);
        qh[ks][2] = ldu(&Qh[(ar + g) * PADK + kb + 8]);
        qh[ks][3] = ldu(&Qh[(ar + g + 8) * PADK + kb + 8]);
        ql[ks][0] = ldu(&Ql[(ar + g) * PADK + kb]);
        ql[ks][1] = ldu(&Ql[(ar + g + 8) * PADK + kb]);
        ql[ks][2] = ldu(&Ql[(ar + g) * PADK + kb + 8]);
        ql[ks][3] = ldu(&Ql[(ar + g + 8) * PADK + kb + 8]);
    }

    float4 o[4];
#pragma unroll
    for (int i = 0; i < 4; i++) o[i] = make_float4(0.f, 0.f, 0.f, 0.f);
    float m0 = -1e30f, m1 = -1e30f, l0 = 0.f, l1 = 0.f;

    for (int s0 = 0; s0 < LQ; s0 += 32) {
        __syncthreads();   // protect K/V from previous iteration's readers
        // stage K [32][32] split; V transposed [hd][key] split
        {
            int row = tid >> 3;            // key 0..31
            int c4  = (tid & 7) * 4;       // hd 0..28
            int off = ((s0 + row) * NB + n) * EDIM + h * HD + c4;
            float4 kv = *(const float4*)&Kb[off];
            split_store4(Kh, Kl, row * PADK + c4, kv);
            float4 vv = *(const float4*)&Vb[off];
            float vf[4] = {vv.x, vv.y, vv.z, vv.w};
#pragma unroll
            for (int j = 0; j < 4; j++) {
                __nv_bfloat16 hi = __float2bfloat16_rn(vf[j]);
                float hf = __bfloat162float(hi);
                Vh[(c4 + j) * PADK + row] = hi;
                Vl[(c4 + j) * PADK + row] = __float2bfloat16_rn(vf[j] - hf);
            }
        }
        __syncthreads();

        // S = Q @ K^T  (32 keys = 4 n-tiles)
        float4 s[4];
#pragma unroll
        for (int i = 0; i < 4; i++) s[i] = make_float4(0.f, 0.f, 0.f, 0.f);
#pragma unroll
        for (int ks = 0; ks < 2; ks++) {
            int kb = ks * 16 + 2 * t;
#pragma unroll
            for (int nt = 0; nt < 4; nt++) {
                int c = nt * 8 + g;    // key index
                unsigned bh0 = ldu(&Kh[c * PADK + kb]);
                unsigned bh1 = ldu(&Kh[c * PADK + kb + 8]);
                unsigned bl0 = ldu(&Kl[c * PADK + kb]);
                unsigned bl1 = ldu(&Kl[c * PADK + kb + 8]);
                mma_bf16(s[nt], qh[ks][0], qh[ks][1], qh[ks][2], qh[ks][3], bh0, bh1);
                mma_bf16(s[nt], qh[ks][0], qh[ks][1], qh[ks][2], qh[ks][3], bl0, bl1);
                mma_bf16(s[nt], ql[ks][0], ql[ks][1], ql[ks][2], ql[ks][3], bh0, bh1);
            }
        }

        // online softmax (rows g and g+8 of this warp's m16 tile)
        float cm0 = fmaxf(fmaxf(s[0].x, s[0].y), fmaxf(s[1].x, s[1].y));
        cm0 = fmaxf(cm0, fmaxf(fmaxf(s[2].x, s[2].y), fmaxf(s[3].x, s[3].y)));
        float cm1 = fmaxf(fmaxf(s[0].z, s[0].w), fmaxf(s[1].z, s[1].w));
        cm1 = fmaxf(cm1, fmaxf(fmaxf(s[2].z, s[2].w), fmaxf(s[3].z, s[3].w)));
        cm0 = fmaxf(cm0, __shfl_xor_sync(0xffffffffu, cm0, 1));
        cm0 = fmaxf(cm0, __shfl_xor_sync(0xffffffffu, cm0, 2));
        cm1 = fmaxf(cm1, __shfl_xor_sync(0xffffffffu, cm1, 1));
        cm1 = fmaxf(cm1, __shfl_xor_sync(0xffffffffu, cm1, 2));

        float mn0 = fmaxf(m0, cm0);
        float mn1 = fmaxf(m1, cm1);
        float c0 = __expf(m0 - mn0);
        float c1 = __expf(m1 - mn1);

        float rs0 = 0.f, rs1 = 0.f;
#pragma unroll
        for (int nt = 0; nt < 4; nt++) {
            s[nt].x = __expf(s[nt].x - mn0);
            s[nt].y = __expf(s[nt].y - mn0);
            s[nt].z = __expf(s[nt].z - mn1);
            s[nt].w = __expf(s[nt].w - mn1);
            rs0 += s[nt].x + s[nt].y;
            rs1 += s[nt].z + s[nt].w;
        }
        rs0 += __shfl_xor_sync(0xffffffffu, rs0, 1);
        rs0 += __shfl_xor_sync(0xffffffffu, rs0, 2);
        rs1 += __shfl_xor_sync(0xffffffffu, rs1, 1);
        rs1 += __shfl_xor_sync(0xffffffffu, rs1, 2);

        l0 = l0 * c0 + rs0;
        l1 = l1 * c1 + rs1;
#pragma unroll
        for (int nt = 0; nt < 4; nt++) {
            o[nt].x *= c0; o[nt].y *= c0;
            o[nt].z *= c1; o[nt].w *= c1;
        }
        m0 = mn0; m1 = mn1;

        // P fragments: C-layout maps exactly to A-layout (FA2 trick), split hi/lo
        unsigned ph[2][4], pl[2][4];
        split_pack2(s[0].x, s[0].y, ph[0][0], pl[0][0]);
        split_pack2(s[0].z, s[0].w, ph[0][1], pl[0][1]);
        split_pack2(s[1].x, s[1].y, ph[0][2], pl[0][2]);
        split_pack2(s[1].z, s[1].w, ph[0][3], pl[0][3]);
        split_pack2(s[2].x, s[2].y, ph[1][0], pl[1][0]);
        split_pack2(s[2].z, s[2].w, ph[1][1], pl[1][1]);
        split_pack2(s[3].x, s[3].y, ph[1][2], pl[1][2]);
        split_pack2(s[3].z, s[3].w, ph[1][3], pl[1][3]);

        // O += P @ V  (V transposed in smem: [hd][key])
#pragma unroll
        for (int ks = 0; ks < 2; ks++) {
            int kb = ks * 16 + 2 * t;  // key offset
#pragma unroll
            for (int nt = 0; nt < 4; nt++) {
                int c = nt * 8 + g;    // hd index
                unsigned bh0 = ldu(&Vh[c * PADK + kb]);
                unsigned bh1 = ldu(&Vh[c * PADK + kb + 8]);
                unsigned bl0 = ldu(&Vl[c * PADK + kb]);
                unsigned bl1 = ldu(&Vl[c * PADK + kb + 8]);
                mma_bf16(o[nt], ph[ks][0], ph[ks][1], ph[ks][2], ph[ks][3], bh0, bh1);
                mma_bf16(o[nt], ph[ks][0], ph[ks][1], ph[ks][2], ph[ks][3], bl0, bl1);
                mma_bf16(o[nt], pl[ks][0], pl[ks][1], pl[ks][2], pl[ks][3], bh0, bh1);
            }
        }
    }

    const float inv0 = 1.f / l0;
    const float inv1 = 1.f / l1;
    const int lrow = qbase + ar + g;
    const int base0 = (lrow * NB + n) * EDIM + h * HD;
    const int base1 = ((lrow + 8) * NB + n) * EDIM + h * HD;
#pragma unroll
    for (int nt = 0; nt < 4; nt++) {
        int col = nt * 8 + 2 * t;
        float2 o0 = make_float2(o[nt].x * inv0, o[nt].y * inv0);
        float2 o1 = make_float2(o[nt].z * inv1, o[nt].w * inv1);
        *(float2*)&Ob[base0 + col] = o0;
        *(float2*)&Ob[base1 + col] = o1;
    }
}

// ---------------------------------------------------------------------------
// Input order = setup_inputs() dict order:
//  0 query, 1 key, 2 value, 3 query_teacher, 4 key_teacher, 5 value_teacher,
//  6 w_q, 7 w_k, 8 w_v, 9 w_q_teacher, 10 w_k_teacher, 11 w_v_teacher,
//  12 w_out, 13 w_out_teacher,
//  14 b_q, 15 b_k, 16 b_v, 17 b_q_teacher, 18 b_k_teacher, 19 b_v_teacher,
//  20 b_out, 21 b_out_teacher
// ---------------------------------------------------------------------------
extern "C" void kernel_launch(void* const* d_in, const int* in_sizes, int n_in,
                              void* d_out, int out_size)
{
    const float* P[22];
    for (int i = 0; i < 22; i++) P[i] = (const float*)d_in[i];

    dim3 gin(2, 64, 6);
    inproj_kernel<<<gin, 256>>>(
        P[0], P[1], P[2], P[3], P[4], P[5],        // activations
        P[6], P[7], P[8],                          // w_q, w_k, w_v
        P[14], P[15], P[16],                       // b_q, b_k, b_v
        P[9], P[10], P[11],                        // w_q_t, w_k_t, w_v_t
        P[17], P[18], P[19]);                      // b_q_t, b_k_t, b_v_t

    dim3 gat(8, 128);               // 8 query blocks x (2 streams * 8 n * 8 h)
    attn_kernel<<<gat, 256>>>();

    dim3 gout(2, 64, 2);
    outproj_kernel<<<gout, 256>>>(
        P[12], P[20],                              // w_out, b_out
        P[13], P[21],                              // w_out_teacher, b_out_teacher
        (float*)d_out);
}

// round 9
// speedup vs baseline: 2.3644x; 1.6658x over previous
#include <cuda_runtime.h>
#include <cuda_bf16.h>

#define TOK   8192   // L*N tokens
#define EDIM  256
#define HD    32
#define NB    8      // batch N
#define LQ    1024   // seq len
#define PADK  40     // bf16 elements per smem row (stride) — conflict-free frag loads

// bf16 hi/lo planes: activations, weights, proj outputs, attention outputs
__device__ __nv_bfloat16 g_xh[6][TOK * EDIM], g_xl[6][TOK * EDIM];
__device__ __nv_bfloat16 g_wh[8][EDIM * EDIM], g_wl[8][EDIM * EDIM];
__device__ __nv_bfloat16 g_ph[6][TOK * EDIM], g_pl[6][TOK * EDIM];
__device__ __nv_bfloat16 g_oh[2][TOK * EDIM], g_ol[2][TOK * EDIM];

// ---------------------------------------------------------------------------
// helpers
// ---------------------------------------------------------------------------
__device__ __forceinline__ void mma_bf16(float4& d,
    unsigned a0, unsigned a1, unsigned a2, unsigned a3,
    unsigned b0, unsigned b1)
{
    asm volatile(
        "mma.sync.aligned.m16n8k16.row.col.f32.bf16.bf16.f32 "
        "{%0,%1,%2,%3}, {%4,%5,%6,%7}, {%8,%9}, {%0,%1,%2,%3};"
        : "+f"(d.x), "+f"(d.y), "+f"(d.z), "+f"(d.w)
        : "r"(a0), "r"(a1), "r"(a2), "r"(a3), "r"(b0), "r"(b1));
}

__device__ __forceinline__ void cp16(void* smem, const void* gmem)
{
    unsigned s = (unsigned)__cvta_generic_to_shared(smem);
    asm volatile("cp.async.ca.shared.global [%0], [%1], 16;" :: "r"(s), "l"(gmem));
}
__device__ __forceinline__ void cp_commit_wait()
{
    asm volatile("cp.async.commit_group;");
    asm volatile("cp.async.wait_group 0;" ::: "memory");
}

__device__ __forceinline__ unsigned ldu(const __nv_bfloat16* p)
{
    return *reinterpret_cast<const unsigned*>(p);
}

// split two floats into packed bf16x2 hi + residual lo
__device__ __forceinline__ void split2(float x, float y,
    __nv_bfloat162& h, __nv_bfloat162& l)
{
    h = __floats2bfloat162_rn(x, y);
    float2 f = __bfloat1622float2(h);
    l = __floats2bfloat162_rn(x - f.x, y - f.y);
}

// ---------------------------------------------------------------------------
// pre-split kernels: fp32 -> bf16 hi/lo planes
// ---------------------------------------------------------------------------
__global__ __launch_bounds__(256) void split_act_kernel(
    const float* a0, const float* a1, const float* a2,
    const float* a3, const float* a4, const float* a5)
{
    const float* src[6] = {a0, a1, a2, a3, a4, a5};
    const int z = blockIdx.z;
    const int i = (blockIdx.x * 256 + threadIdx.x) * 4;
    float4 v = *(const float4*)&src[z][i];
    __nv_bfloat162 h01, l01, h23, l23;
    split2(v.x, v.y, h01, l01);
    split2(v.z, v.w, h23, l23);
    *(__nv_bfloat162*)&g_xh[z][i]     = h01;
    *(__nv_bfloat162*)&g_xh[z][i + 2] = h23;
    *(__nv_bfloat162*)&g_xl[z][i]     = l01;
    *(__nv_bfloat162*)&g_xl[z][i + 2] = l23;
}

__global__ __launch_bounds__(256) void split_w_kernel(
    const float* w0, const float* w1, const float* w2, const float* w3,
    const float* w4, const float* w5, const float* w6, const float* w7)
{
    const float* src[8] = {w0, w1, w2, w3, w4, w5, w6, w7};
    const int z = blockIdx.z;
    const int i = (blockIdx.x * 256 + threadIdx.x) * 4;
    float4 v = *(const float4*)&src[z][i];
    __nv_bfloat162 h01, l01, h23, l23;
    split2(v.x, v.y, h01, l01);
    split2(v.z, v.w, h23, l23);
    *(__nv_bfloat162*)&g_wh[z][i]     = h01;
    *(__nv_bfloat162*)&g_wh[z][i + 2] = h23;
    *(__nv_bfloat162*)&g_wl[z][i]     = l01;
    *(__nv_bfloat162*)&g_wl[z][i + 2] = l23;
}

// ---------------------------------------------------------------------------
// GEMM core: C[M,256] = X @ W^T + bias, bf16x3 split MMA, cp.async staging.
// CTA tile 128x128, 8 warps (4m x 2n), warp tile 32x64.
// Output either split bf16 planes (Ch/Cl) or fp32 (Cf).
// ---------------------------------------------------------------------------
__device__ __forceinline__ void gemm_core(
    const __nv_bfloat16* __restrict__ Xh, const __nv_bfloat16* __restrict__ Xl,
    const __nv_bfloat16* __restrict__ Wh, const __nv_bfloat16* __restrict__ Wl,
    const float* __restrict__ bias,
    __nv_bfloat16* __restrict__ Ch, __nv_bfloat16* __restrict__ Cl,
    float* __restrict__ Cf)
{
    __shared__ __nv_bfloat16 sXh[128 * PADK], sXl[128 * PADK];
    __shared__ __nv_bfloat16 sWh[128 * PADK], sWl[128 * PADK];

    const int tid  = threadIdx.x;
    const int wid  = tid >> 5;
    const int lane = tid & 31;
    const int g = lane >> 2, t = lane & 3;
    const int wm = (wid >> 1) * 32;
    const int wn = (wid & 1) * 64;
    const int m0 = blockIdx.y * 128;
    const int n0 = blockIdx.x * 128;

    float4 acc[2][8];
#pragma unroll
    for (int i = 0; i < 2; i++)
#pragma unroll
        for (int j = 0; j < 8; j++) acc[i][j] = make_float4(0.f, 0.f, 0.f, 0.f);

    for (int k0 = 0; k0 < EDIM; k0 += 32) {
        // stage X/W tiles [128][32] bf16 x 4 planes via cp.async
#pragma unroll
        for (int i = 0; i < 2; i++) {
            int id  = tid + i * 256;
            int row = id >> 2;
            int ck  = (id & 3) * 8;          // bf16 col in tile
            size_t gx = (size_t)(m0 + row) * EDIM + k0 + ck;
            size_t gw = (size_t)(n0 + row) * EDIM + k0 + ck;
            cp16(&sXh[row * PADK + ck], Xh + gx);
            cp16(&sXl[row * PADK + ck], Xl + gx);
            cp16(&sWh[row * PADK + ck], Wh + gw);
            cp16(&sWl[row * PADK + ck], Wl + gw);
        }
        cp_commit_wait();
        __syncthreads();

#pragma unroll
        for (int ks = 0; ks < 2; ks++) {
            const int kb = ks * 16 + 2 * t;
            unsigned ah[2][4], al[2][4];
#pragma unroll
            for (int mt = 0; mt < 2; mt++) {
                int r = wm + mt * 16 + g;
                ah[mt][0] = ldu(&sXh[r * PADK + kb]);
                ah[mt][1] = ldu(&sXh[(r + 8) * PADK + kb]);
                ah[mt][2] = ldu(&sXh[r * PADK + kb + 8]);
                ah[mt][3] = ldu(&sXh[(r + 8) * PADK + kb + 8]);
                al[mt][0] = ldu(&sXl[r * PADK + kb]);
                al[mt][1] = ldu(&sXl[(r + 8) * PADK + kb]);
                al[mt][2] = ldu(&sXl[r * PADK + kb + 8]);
                al[mt][3] = ldu(&sXl[(r + 8) * PADK + kb + 8]);
            }
#pragma unroll
            for (int nt = 0; nt < 8; nt++) {
                int c = wn + nt * 8 + g;
                unsigned bh0 = ldu(&sWh[c * PADK + kb]);
                unsigned bh1 = ldu(&sWh[c * PADK + kb + 8]);
                unsigned bl0 = ldu(&sWl[c * PADK + kb]);
                unsigned bl1 = ldu(&sWl[c * PADK + kb + 8]);
#pragma unroll
                for (int mt = 0; mt < 2; mt++) {
                    mma_bf16(acc[mt][nt], ah[mt][0], ah[mt][1], ah[mt][2], ah[mt][3], bh0, bh1);
                    mma_bf16(acc[mt][nt], ah[mt][0], ah[mt][1], ah[mt][2], ah[mt][3], bl0, bl1);
                    mma_bf16(acc[mt][nt], al[mt][0], al[mt][1], al[mt][2], al[mt][3], bh0, bh1);
                }
            }
        }
        __syncthreads();
    }

#pragma unroll
    for (int mt = 0; mt < 2; mt++)
#pragma unroll
        for (int nt = 0; nt < 8; nt++) {
            int row = m0 + wm + mt * 16 + g;
            int col = n0 + wn + nt * 8 + 2 * t;
            float2 bb = *(const float2*)&bias[col];
            float4 a = acc[mt][nt];
            float v0x = a.x + bb.x, v0y = a.y + bb.y;
            float v1x = a.z + bb.x, v1y = a.w + bb.y;
            if (Cf) {
                *(float2*)&Cf[(size_t)row * EDIM + col] = make_float2(v0x, v0y);
                *(float2*)&Cf[(size_t)(row + 8) * EDIM + col] = make_float2(v1x, v1y);
            } else {
                __nv_bfloat162 h0, l0, h1, l1;
                split2(v0x, v0y, h0, l0);
                split2(v1x, v1y, h1, l1);
                *(__nv_bfloat162*)&Ch[(size_t)row * EDIM + col] = h0;
                *(__nv_bfloat162*)&Cl[(size_t)row * EDIM + col] = l0;
                *(__nv_bfloat162*)&Ch[(size_t)(row + 8) * EDIM + col] = h1;
                *(__nv_bfloat162*)&Cl[(size_t)(row + 8) * EDIM + col] = l1;
            }
        }
}

__global__ __launch_bounds__(256, 2) void inproj_kernel(
    const float* b0, const float* b1, const float* b2,
    const float* b3, const float* b4, const float* b5)
{
    const float* Bs[6] = {b0, b1, b2, b3, b4, b5};
    const int z = blockIdx.z;
    gemm_core(g_xh[z], g_xl[z], g_wh[z], g_wl[z], Bs[z],
              g_ph[z], g_pl[z], nullptr);
}

__global__ __launch_bounds__(256, 2) void outproj_kernel(
    const float* bo, const float* bot, float* out)
{
    const int z = blockIdx.z;
    gemm_core(g_oh[z], g_ol[z], g_wh[6 + z], g_wl[6 + z], z ? bot : bo,
              nullptr, nullptr, out + (size_t)z * TOK * EDIM);
}

// ---------------------------------------------------------------------------
// Flash attention, bf16x3 MMA, pre-split inputs, scale applied to S.
// CTA: 128 q rows, 8 warps (one m16 tile each), key chunks of 32.
// ---------------------------------------------------------------------------
__global__ __launch_bounds__(256, 2) void attn_kernel()
{
    __shared__ __nv_bfloat16 sQh[128 * PADK], sQl[128 * PADK];
    __shared__ __nv_bfloat16 sKh[32 * PADK],  sKl[32 * PADK];
    __shared__ __nv_bfloat16 sVh[32 * PADK],  sVl[32 * PADK];  // transposed [hd][key]

    const int tid  = threadIdx.x;
    const int wid  = tid >> 5;
    const int lane = tid & 31;
    const int g = lane >> 2, t = lane & 3;

    const int idx    = blockIdx.y;
    const int stream = idx >> 6;
    const int n      = (idx >> 3) & 7;
    const int h      = idx & 7;

    const __nv_bfloat16* __restrict__ Qhg = g_ph[stream * 3 + 0];
    const __nv_bfloat16* __restrict__ Qlg = g_pl[stream * 3 + 0];
    const __nv_bfloat16* __restrict__ Khg = g_ph[stream * 3 + 1];
    const __nv_bfloat16* __restrict__ Klg = g_pl[stream * 3 + 1];
    const __nv_bfloat16* __restrict__ Vhg = g_ph[stream * 3 + 2];
    const __nv_bfloat16* __restrict__ Vlg = g_pl[stream * 3 + 2];
    __nv_bfloat16* __restrict__ Oh = g_oh[stream];
    __nv_bfloat16* __restrict__ Ol = g_ol[stream];

    const int qbase = blockIdx.x * 128;
    const float scale = 0.17677669529663687f;   // 1/sqrt(32)

    // stage Q via cp.async (rows 128 x 32 bf16, 2 planes)
#pragma unroll
    for (int i = 0; i < 2; i++) {
        int id  = tid + i * 256;
        int row = id >> 2;
        int ck  = (id & 3) * 8;
        size_t gq = (size_t)((qbase + row) * NB + n) * EDIM + h * HD + ck;
        cp16(&sQh[row * PADK + ck], Qhg + gq);
        cp16(&sQl[row * PADK + ck], Qlg + gq);
    }
    cp_commit_wait();
    __syncthreads();

    // per-warp persistent Q fragments: 2 k-steps of k16
    unsigned qh[2][4], ql[2][4];
    const int ar = wid * 16;
#pragma unroll
    for (int ks = 0; ks < 2; ks++) {
        int kb = ks * 16 + 2 * t;
        qh[ks][0] = ldu(&sQh[(ar + g) * PADK + kb]);
        qh[ks][1] = ldu(&sQh[(ar + g + 8) * PADK + kb]);
        qh[ks][2] = ldu(&sQh[(ar + g) * PADK + kb + 8]);
        qh[ks][3] = ldu(&sQh[(ar + g + 8) * PADK + kb + 8]);
        ql[ks][0] = ldu(&sQl[(ar + g) * PADK + kb]);
        ql[ks][1] = ldu(&sQl[(ar + g + 8) * PADK + kb]);
        ql[ks][2] = ldu(&sQl[(ar + g) * PADK + kb + 8]);
        ql[ks][3] = ldu(&sQl[(ar + g + 8) * PADK + kb + 8]);
    }

    float4 o[4];
#pragma unroll
    for (int i = 0; i < 4; i++) o[i] = make_float4(0.f, 0.f, 0.f, 0.f);
    float m0 = -1e30f, m1 = -1e30f, l0 = 0.f, l1 = 0.f;

    for (int s0 = 0; s0 < LQ; s0 += 32) {
        __syncthreads();   // previous chunk's readers done
        // K rows via cp.async (first 128 threads), V transposed scalar (all)
        if (tid < 128) {
            int row = tid >> 2;
            int ck  = (tid & 3) * 8;
            size_t gk = (size_t)((s0 + row) * NB + n) * EDIM + h * HD + ck;
            cp16(&sKh[row * PADK + ck], Khg + gk);
            cp16(&sKl[row * PADK + ck], Klg + gk);
        }
        {
            int key = tid >> 3;
            int hd0 = (tid & 7) * 4;
            size_t gv = (size_t)((s0 + key) * NB + n) * EDIM + h * HD + hd0;
            uint2 rh = *(const uint2*)(Vhg + gv);
            uint2 rl = *(const uint2*)(Vlg + gv);
            __nv_bfloat16 eh[4], el[4];
            *(uint2*)eh = rh; *(uint2*)el = rl;
#pragma unroll
            for (int j = 0; j < 4; j++) {
                sVh[(hd0 + j) * PADK + key] = eh[j];
                sVl[(hd0 + j) * PADK + key] = el[j];
            }
        }
        cp_commit_wait();
        __syncthreads();

        // S = Q @ K^T  (32 keys = 4 n-tiles)
        float4 s[4];
#pragma unroll
        for (int i = 0; i < 4; i++) s[i] = make_float4(0.f, 0.f, 0.f, 0.f);
#pragma unroll
        for (int ks = 0; ks < 2; ks++) {
            int kb = ks * 16 + 2 * t;
#pragma unroll
            for (int nt = 0; nt < 4; nt++) {
                int c = nt * 8 + g;    // key index
                unsigned bh0 = ldu(&sKh[c * PADK + kb]);
                unsigned bh1 = ldu(&sKh[c * PADK + kb + 8]);
                unsigned bl0 = ldu(&sKl[c * PADK + kb]);
                unsigned bl1 = ldu(&sKl[c * PADK + kb + 8]);
                mma_bf16(s[nt], qh[ks][0], qh[ks][1], qh[ks][2], qh[ks][3], bh0, bh1);
                mma_bf16(s[nt], qh[ks][0], qh[ks][1], qh[ks][2], qh[ks][3], bl0, bl1);
                mma_bf16(s[nt], ql[ks][0], ql[ks][1], ql[ks][2], ql[ks][3], bh0, bh1);
            }
        }
        // apply softmax scale post-MMA (equivalent to scaling Q)
#pragma unroll
        for (int nt = 0; nt < 4; nt++) {
            s[nt].x *= scale; s[nt].y *= scale;
            s[nt].z *= scale; s[nt].w *= scale;
        }

        // online softmax (rows g and g+8 of this warp's m16 tile)
        float cm0 = fmaxf(fmaxf(s[0].x, s[0].y), fmaxf(s[1].x, s[1].y));
        cm0 = fmaxf(cm0, fmaxf(fmaxf(s[2].x, s[2].y), fmaxf(s[3].x, s[3].y)));
        float cm1 = fmaxf(fmaxf(s[0].z, s[0].w), fmaxf(s[1].z, s[1].w));
        cm1 = fmaxf(cm1, fmaxf(fmaxf(s[2].z, s[2].w), fmaxf(s[3].z, s[3].w)));
        cm0 = fmaxf(cm0, __shfl_xor_sync(0xffffffffu, cm0, 1));
        cm0 = fmaxf(cm0, __shfl_xor_sync(0xffffffffu, cm0, 2));
        cm1 = fmaxf(cm1, __shfl_xor_sync(0xffffffffu, cm1, 1));
        cm1 = fmaxf(cm1, __shfl_xor_sync(0xffffffffu, cm1, 2));

        float mn0 = fmaxf(m0, cm0);
        float mn1 = fmaxf(m1, cm1);
        float c0 = __expf(m0 - mn0);
        float c1 = __expf(m1 - mn1);

        float rs0 = 0.f, rs1 = 0.f;
#pragma unroll
        for (int nt = 0; nt < 4; nt++) {
            s[nt].x = __expf(s[nt].x - mn0);
            s[nt].y = __expf(s[nt].y - mn0);
            s[nt].z = __expf(s[nt].z - mn1);
            s[nt].w = __expf(s[nt].w - mn1);
            rs0 += s[nt].x + s[nt].y;
            rs1 += s[nt].z + s[nt].w;
        }
        rs0 += __shfl_xor_sync(0xffffffffu, rs0, 1);
        rs0 += __shfl_xor_sync(0xffffffffu, rs0, 2);
        rs1 += __shfl_xor_sync(0xffffffffu, rs1, 1);
        rs1 += __shfl_xor_sync(0xffffffffu, rs1, 2);

        l0 = l0 * c0 + rs0;
        l1 = l1 * c1 + rs1;
#pragma unroll
        for (int nt = 0; nt < 4; nt++) {
            o[nt].x *= c0; o[nt].y *= c0;
            o[nt].z *= c1; o[nt].w *= c1;
        }
        m0 = mn0; m1 = mn1;

        // P fragments: C-layout == A-layout (FA2), split hi/lo in registers
        __nv_bfloat162 hh, lll;
        unsigned ph[2][4], pl[2][4];
        split2(s[0].x, s[0].y, hh, lll); ph[0][0] = *(unsigned*)&hh; pl[0][0] = *(unsigned*)&lll;
        split2(s[0].z, s[0].w, hh, lll); ph[0][1] = *(unsigned*)&hh; pl[0][1] = *(unsigned*)&lll;
        split2(s[1].x, s[1].y, hh, lll); ph[0][2] = *(unsigned*)&hh; pl[0][2] = *(unsigned*)&lll;
        split2(s[1].z, s[1].w, hh, lll); ph[0][3] = *(unsigned*)&hh; pl[0][3] = *(unsigned*)&lll;
        split2(s[2].x, s[2].y, hh, lll); ph[1][0] = *(unsigned*)&hh; pl[1][0] = *(unsigned*)&lll;
        split2(s[2].z, s[2].w, hh, lll); ph[1][1] = *(unsigned*)&hh; pl[1][1] = *(unsigned*)&lll;
        split2(s[3].x, s[3].y, hh, lll); ph[1][2] = *(unsigned*)&hh; pl[1][2] = *(unsigned*)&lll;
        split2(s[3].z, s[3].w, hh, lll); ph[1][3] = *(unsigned*)&hh; pl[1][3] = *(unsigned*)&lll;

        // O += P @ V  (V transposed in smem: [hd][key])
#pragma unroll
        for (int ks = 0; ks < 2; ks++) {
            int kb = ks * 16 + 2 * t;  // key offset
#pragma unroll
            for (int nt = 0; nt < 4; nt++) {
                int c = nt * 8 + g;    // hd index
                unsigned bh0 = ldu(&sVh[c * PADK + kb]);
                unsigned bh1 = ldu(&sVh[c * PADK + kb + 8]);
                unsigned bl0 = ldu(&sVl[c * PADK + kb]);
                unsigned bl1 = ldu(&sVl[c * PADK + kb + 8]);
                mma_bf16(o[nt], ph[ks][0], ph[ks][1], ph[ks][2], ph[ks][3], bh0, bh1);
                mma_bf16(o[nt], ph[ks][0], ph[ks][1], ph[ks][2], ph[ks][3], bl0, bl1);
                mma_bf16(o[nt], pl[ks][0], pl[ks][1], pl[ks][2], pl[ks][3], bh0, bh1);
            }
        }
    }

    const float inv0 = 1.f / l0;
    const float inv1 = 1.f / l1;
    const int lrow = qbase + ar + g;
    const size_t base0 = (size_t)(lrow * NB + n) * EDIM + h * HD;
    const size_t base1 = (size_t)((lrow + 8) * NB + n) * EDIM + h * HD;
#pragma unroll
    for (int nt = 0; nt < 4; nt++) {
        int col = nt * 8 + 2 * t;
        __nv_bfloat162 h0, l0b, h1, l1b;
        split2(o[nt].x * inv0, o[nt].y * inv0, h0, l0b);
        split2(o[nt].z * inv1, o[nt].w * inv1, h1, l1b);
        *(__nv_bfloat162*)&Oh[base0 + col] = h0;
        *(__nv_bfloat162*)&Ol[base0 + col] = l0b;
        *(__nv_bfloat162*)&Oh[base1 + col] = h1;
        *(__nv_bfloat162*)&Ol[base1 + col] = l1b;
    }
}

// ---------------------------------------------------------------------------
// Input order = setup_inputs() dict order:
//  0 query, 1 key, 2 value, 3 query_teacher, 4 key_teacher, 5 value_teacher,
//  6 w_q, 7 w_k, 8 w_v, 9 w_q_teacher, 10 w_k_teacher, 11 w_v_teacher,
//  12 w_out, 13 w_out_teacher,
//  14 b_q, 15 b_k, 16 b_v, 17 b_q_teacher, 18 b_k_teacher, 19 b_v_teacher,
//  20 b_out, 21 b_out_teacher
// ---------------------------------------------------------------------------
extern "C" void kernel_launch(void* const* d_in, const int* in_sizes, int n_in,
                              void* d_out, int out_size)
{
    const float* P[22];
    for (int i = 0; i < 22; i++) P[i] = (const float*)d_in[i];

    // pre-split fp32 -> bf16 hi/lo
    dim3 gsa(TOK * EDIM / (4 * 256), 1, 6);
    split_act_kernel<<<gsa, 256>>>(P[0], P[1], P[2], P[3], P[4], P[5]);
    dim3 gsw(EDIM * EDIM / (4 * 256), 1, 8);
    split_w_kernel<<<gsw, 256>>>(P[6], P[7], P[8], P[9], P[10], P[11],
                                 P[12], P[13]);

    dim3 gin(2, 64, 6);
    inproj_kernel<<<gin, 256>>>(P[14], P[15], P[16], P[17], P[18], P[19]);

    dim3 gat(8, 128);               // 8 q-blocks x (2 streams * 8 n * 8 h)
    attn_kernel<<<gat, 256>>>();

    dim3 gout(2, 64, 2);
    outproj_kernel<<<gout, 256>>>(P[20], P[21], (float*)d_out);
}

// round 13
// speedup vs baseline: 2.6132x; 1.1052x over previous
#include <cuda_runtime.h>
#include <cuda_bf16.h>

#define TOK   8192   // L*N tokens
#define EDIM  256
#define HD    32
#define NB    8      // batch N
#define LQ    1024   // seq len
#define PADK  40     // bf16 elements per smem row (stride) — conflict-free frag loads

// bf16 hi/lo planes: activations, weights, proj outputs, attention outputs
__device__ __nv_bfloat16 g_xh[6][TOK * EDIM], g_xl[6][TOK * EDIM];
__device__ __nv_bfloat16 g_wh[8][EDIM * EDIM], g_wl[8][EDIM * EDIM];
__device__ __nv_bfloat16 g_ph[6][TOK * EDIM], g_pl[6][TOK * EDIM];
__device__ __nv_bfloat16 g_oh[2][TOK * EDIM], g_ol[2][TOK * EDIM];

// ---------------------------------------------------------------------------
// helpers
// ---------------------------------------------------------------------------
__device__ __forceinline__ void mma_bf16(float4& d,
    unsigned a0, unsigned a1, unsigned a2, unsigned a3,
    unsigned b0, unsigned b1)
{
    asm volatile(
        "mma.sync.aligned.m16n8k16.row.col.f32.bf16.bf16.f32 "
        "{%0,%1,%2,%3}, {%4,%5,%6,%7}, {%8,%9}, {%0,%1,%2,%3};"
        : "+f"(d.x), "+f"(d.y), "+f"(d.z), "+f"(d.w)
        : "r"(a0), "r"(a1), "r"(a2), "r"(a3), "r"(b0), "r"(b1));
}

__device__ __forceinline__ void cp16(void* smem, const void* gmem)
{
    unsigned s = (unsigned)__cvta_generic_to_shared(smem);
    asm volatile("cp.async.ca.shared.global [%0], [%1], 16;" :: "r"(s), "l"(gmem));
}
__device__ __forceinline__ void cp_commit()
{
    asm volatile("cp.async.commit_group;");
}
__device__ __forceinline__ void cp_wait0()
{
    asm volatile("cp.async.wait_group 0;" ::: "memory");
}

__device__ __forceinline__ unsigned ldu(const __nv_bfloat16* p)
{
    return *reinterpret_cast<const unsigned*>(p);
}

// split two floats into packed bf16x2 hi + residual lo
__device__ __forceinline__ void split2(float x, float y,
    __nv_bfloat162& h, __nv_bfloat162& l)
{
    h = __floats2bfloat162_rn(x, y);
    float2 f = __bfloat1622float2(h);
    l = __floats2bfloat162_rn(x - f.x, y - f.y);
}

// ---------------------------------------------------------------------------
// pre-split kernels: fp32 -> bf16 hi/lo planes
// ---------------------------------------------------------------------------
__global__ __launch_bounds__(256) void split_act_kernel(
    const float* a0, const float* a1, const float* a2,
    const float* a3, const float* a4, const float* a5)
{
    const float* src[6] = {a0, a1, a2, a3, a4, a5};
    const int z = blockIdx.z;
    const int i = (blockIdx.x * 256 + threadIdx.x) * 4;
    float4 v = *(const float4*)&src[z][i];
    __nv_bfloat162 h01, l01, h23, l23;
    split2(v.x, v.y, h01, l01);
    split2(v.z, v.w, h23, l23);
    *(__nv_bfloat162*)&g_xh[z][i]     = h01;
    *(__nv_bfloat162*)&g_xh[z][i + 2] = h23;
    *(__nv_bfloat162*)&g_xl[z][i]     = l01;
    *(__nv_bfloat162*)&g_xl[z][i + 2] = l23;
}

__global__ __launch_bounds__(256) void split_w_kernel(
    const float* w0, const float* w1, const float* w2, const float* w3,
    const float* w4, const float* w5, const float* w6, const float* w7)
{
    const float* src[8] = {w0, w1, w2, w3, w4, w5, w6, w7};
    const int z = blockIdx.z;
    const int i = (blockIdx.x * 256 + threadIdx.x) * 4;
    float4 v = *(const float4*)&src[z][i];
    __nv_bfloat162 h01, l01, h23, l23;
    split2(v.x, v.y, h01, l01);
    split2(v.z, v.w, h23, l23);
    *(__nv_bfloat162*)&g_wh[z][i]     = h01;
    *(__nv_bfloat162*)&g_wh[z][i + 2] = h23;
    *(__nv_bfloat162*)&g_wl[z][i]     = l01;
    *(__nv_bfloat162*)&g_wl[z][i + 2] = l23;
}

// ---------------------------------------------------------------------------
// GEMM core: C[M,256] = X @ W^T + bias, bf16x3 split MMA, cp.async staging.
// CTA tile 128x128, 8 warps (4m x 2n), warp tile 32x64.
// Output either split bf16 planes (Ch/Cl) or fp32 (Cf).
// ---------------------------------------------------------------------------
__device__ __forceinline__ void gemm_core(
    const __nv_bfloat16* __restrict__ Xh, const __nv_bfloat16* __restrict__ Xl,
    const __nv_bfloat16* __restrict__ Wh, const __nv_bfloat16* __restrict__ Wl,
    const float* __restrict__ bias,
    __nv_bfloat16* __restrict__ Ch, __nv_bfloat16* __restrict__ Cl,
    float* __restrict__ Cf)
{
    __shared__ __nv_bfloat16 sXh[128 * PADK], sXl[128 * PADK];
    __shared__ __nv_bfloat16 sWh[128 * PADK], sWl[128 * PADK];

    const int tid  = threadIdx.x;
    const int wid  = tid >> 5;
    const int lane = tid & 31;
    const int g = lane >> 2, t = lane & 3;
    const int wm = (wid >> 1) * 32;
    const int wn = (wid & 1) * 64;
    const int m0 = blockIdx.y * 128;
    const int n0 = blockIdx.x * 128;

    float4 acc[2][8];
#pragma unroll
    for (int i = 0; i < 2; i++)
#pragma unroll
        for (int j = 0; j < 8; j++) acc[i][j] = make_float4(0.f, 0.f, 0.f, 0.f);

    for (int k0 = 0; k0 < EDIM; k0 += 32) {
        // stage X/W tiles [128][32] bf16 x 4 planes via cp.async
#pragma unroll
        for (int i = 0; i < 2; i++) {
            int id  = tid + i * 256;
            int row = id >> 2;
            int ck  = (id & 3) * 8;          // bf16 col in tile
            size_t gx = (size_t)(m0 + row) * EDIM + k0 + ck;
            size_t gw = (size_t)(n0 + row) * EDIM + k0 + ck;
            cp16(&sXh[row * PADK + ck], Xh + gx);
            cp16(&sXl[row * PADK + ck], Xl + gx);
            cp16(&sWh[row * PADK + ck], Wh + gw);
            cp16(&sWl[row * PADK + ck], Wl + gw);
        }
        cp_commit();
        cp_wait0();
        __syncthreads();

#pragma unroll
        for (int ks = 0; ks < 2; ks++) {
            const int kb = ks * 16 + 2 * t;
            unsigned ah[2][4], al[2][4];
#pragma unroll
            for (int mt = 0; mt < 2; mt++) {
                int r = wm + mt * 16 + g;
                ah[mt][0] = ldu(&sXh[r * PADK + kb]);
                ah[mt][1] = ldu(&sXh[(r + 8) * PADK + kb]);
                ah[mt][2] = ldu(&sXh[r * PADK + kb + 8]);
                ah[mt][3] = ldu(&sXh[(r + 8) * PADK + kb + 8]);
                al[mt][0] = ldu(&sXl[r * PADK + kb]);
                al[mt][1] = ldu(&sXl[(r + 8) * PADK + kb]);
                al[mt][2] = ldu(&sXl[r * PADK + kb + 8]);
                al[mt][3] = ldu(&sXl[(r + 8) * PADK + kb + 8]);
            }
#pragma unroll
            for (int nt = 0; nt < 8; nt++) {
                int c = wn + nt * 8 + g;
                unsigned bh0 = ldu(&sWh[c * PADK + kb]);
                unsigned bh1 = ldu(&sWh[c * PADK + kb + 8]);
                unsigned bl0 = ldu(&sWl[c * PADK + kb]);
                unsigned bl1 = ldu(&sWl[c * PADK + kb + 8]);
#pragma unroll
                for (int mt = 0; mt < 2; mt++) {
                    mma_bf16(acc[mt][nt], ah[mt][0], ah[mt][1], ah[mt][2], ah[mt][3], bh0, bh1);
                    mma_bf16(acc[mt][nt], ah[mt][0], ah[mt][1], ah[mt][2], ah[mt][3], bl0, bl1);
                    mma_bf16(acc[mt][nt], al[mt][0], al[mt][1], al[mt][2], al[mt][3], bh0, bh1);
                }
            }
        }
        __syncthreads();
    }

#pragma unroll
    for (int mt = 0; mt < 2; mt++)
#pragma unroll
        for (int nt = 0; nt < 8; nt++) {
            int row = m0 + wm + mt * 16 + g;
            int col = n0 + wn + nt * 8 + 2 * t;
            float2 bb = *(const float2*)&bias[col];
            float4 a = acc[mt][nt];
            float v0x = a.x + bb.x, v0y = a.y + bb.y;
            float v1x = a.z + bb.x, v1y = a.w + bb.y;
            if (Cf) {
                *(float2*)&Cf[(size_t)row * EDIM + col] = make_float2(v0x, v0y);
                *(float2*)&Cf[(size_t)(row + 8) * EDIM + col] = make_float2(v1x, v1y);
            } else {
                __nv_bfloat162 h0, l0, h1, l1;
                split2(v0x, v0y, h0, l0);
                split2(v1x, v1y, h1, l1);
                *(__nv_bfloat162*)&Ch[(size_t)row * EDIM + col] = h0;
                *(__nv_bfloat162*)&Cl[(size_t)row * EDIM + col] = l0;
                *(__nv_bfloat162*)&Ch[(size_t)(row + 8) * EDIM + col] = h1;
                *(__nv_bfloat162*)&Cl[(size_t)(row + 8) * EDIM + col] = l1;
            }
        }
}

__global__ __launch_bounds__(256, 2) void inproj_kernel(
    const float* b0, const float* b1, const float* b2,
    const float* b3, const float* b4, const float* b5)
{
    const float* Bs[6] = {b0, b1, b2, b3, b4, b5};
    const int z = blockIdx.z;
    gemm_core(g_xh[z], g_xl[z], g_wh[z], g_wl[z], Bs[z],
              g_ph[z], g_pl[z], nullptr);
}

__global__ __launch_bounds__(256, 2) void outproj_kernel(
    const float* bo, const float* bot, float* out)
{
    const int z = blockIdx.z;
    gemm_core(g_oh[z], g_ol[z], g_wh[6 + z], g_wl[6 + z], z ? bot : bo,
              nullptr, nullptr, out + (size_t)z * TOK * EDIM);
}

// ---------------------------------------------------------------------------
// Flash attention, bf16x3 MMA, double-buffered K/V pipeline, exp2 softmax.
// CTA: 128 q rows, 8 warps (one m16 tile each), key chunks of 32.
// ---------------------------------------------------------------------------
__global__ __launch_bounds__(256, 2) void attn_kernel()
{
    __shared__ __nv_bfloat16 sQh[128 * PADK], sQl[128 * PADK];
    __shared__ __nv_bfloat16 sKh[2][32 * PADK], sKl[2][32 * PADK];
    __shared__ __nv_bfloat16 sVh[2][32 * PADK], sVl[2][32 * PADK]; // [hd][key]

    const int tid  = threadIdx.x;
    const int wid  = tid >> 5;
    const int lane = tid & 31;
    const int g = lane >> 2, t = lane & 3;

    const int idx    = blockIdx.y;
    const int stream = idx >> 6;
    const int n      = (idx >> 3) & 7;
    const int h      = idx & 7;

    const __nv_bfloat16* __restrict__ Qhg = g_ph[stream * 3 + 0];
    const __nv_bfloat16* __restrict__ Qlg = g_pl[stream * 3 + 0];
    const __nv_bfloat16* __restrict__ Khg = g_ph[stream * 3 + 1];
    const __nv_bfloat16* __restrict__ Klg = g_pl[stream * 3 + 1];
    const __nv_bfloat16* __restrict__ Vhg = g_ph[stream * 3 + 2];
    const __nv_bfloat16* __restrict__ Vlg = g_pl[stream * 3 + 2];
    __nv_bfloat16* __restrict__ Oh = g_oh[stream];
    __nv_bfloat16* __restrict__ Ol = g_ol[stream];

    const int qbase = blockIdx.x * 128;
    // softmax in base-2 domain: s2 = (q.k) * scale * log2(e)
    const float scl2 = 0.17677669529663687f * 1.4426950408889634f;

    // K staging coords (threads 0..127): row=key, ck=bf16 col
    const int krow = tid >> 2;
    const int kck  = (tid & 3) * 8;
    // V staging coords (all 256): key, hd quad
    const int vkey = tid >> 3;
    const int vhd0 = (tid & 7) * 4;

    // ---- prologue: stage Q + K chunk 0, load V chunk 0 regs ----
#pragma unroll
    for (int i = 0; i < 2; i++) {
        int id  = tid + i * 256;
        int row = id >> 2;
        int ck  = (id & 3) * 8;
        size_t gq = (size_t)((qbase + row) * NB + n) * EDIM + h * HD + ck;
        cp16(&sQh[row * PADK + ck], Qhg + gq);
        cp16(&sQl[row * PADK + ck], Qlg + gq);
    }
    if (tid < 128) {
        size_t gk = (size_t)(krow * NB + n) * EDIM + h * HD + kck;
        cp16(&sKh[0][krow * PADK + kck], Khg + gk);
        cp16(&sKl[0][krow * PADK + kck], Klg + gk);
    }
    cp_commit();
    uint2 vh_cur, vl_cur;
    {
        size_t gv = (size_t)(vkey * NB + n) * EDIM + h * HD + vhd0;
        vh_cur = *(const uint2*)(Vhg + gv);
        vl_cur = *(const uint2*)(Vlg + gv);
    }
    cp_wait0();
    __syncthreads();

    // per-warp persistent Q fragments: 2 k-steps of k16
    unsigned qh[2][4], ql[2][4];
    const int ar = wid * 16;
#pragma unroll
    for (int ks = 0; ks < 2; ks++) {
        int kb = ks * 16 + 2 * t;
        qh[ks][0] = ldu(&sQh[(ar + g) * PADK + kb]);
        qh[ks][1] = ldu(&sQh[(ar + g + 8) * PADK + kb]);
        qh[ks][2] = ldu(&sQh[(ar + g) * PADK + kb + 8]);
        qh[ks][3] = ldu(&sQh[(ar + g + 8) * PADK + kb + 8]);
        ql[ks][0] = ldu(&sQl[(ar + g) * PADK + kb]);
        ql[ks][1] = ldu(&sQl[(ar + g + 8) * PADK + kb]);
        ql[ks][2] = ldu(&sQl[(ar + g) * PADK + kb + 8]);
        ql[ks][3] = ldu(&sQl[(ar + g + 8) * PADK + kb + 8]);
    }

    float4 o[4];
#pragma unroll
    for (int i = 0; i < 4; i++) o[i] = make_float4(0.f, 0.f, 0.f, 0.f);
    float m0 = -1e30f, m1 = -1e30f, l0 = 0.f, l1 = 0.f;

    for (int ci = 0; ci < 32; ci++) {
        const int buf = ci & 1;
        if (ci) cp_wait0();           // K(ci) landed (issued last iteration)

        // V(ci) transpose store from regs (loaded last iteration / prologue)
        {
            __nv_bfloat16 eh[4], el[4];
            *(uint2*)eh = vh_cur; *(uint2*)el = vl_cur;
#pragma unroll
            for (int j = 0; j < 4; j++) {
                sVh[buf][(vhd0 + j) * PADK + vkey] = eh[j];
                sVl[buf][(vhd0 + j) * PADK + vkey] = el[j];
            }
        }
        __syncthreads();   // K(ci)+V(ci) visible; compute(ci-1) readers retired

        // prefetch chunk ci+1 (overlaps with compute below)
        if (ci + 1 < 32) {
            const int s1 = (ci + 1) * 32;
            if (tid < 128) {
                size_t gk = (size_t)((s1 + krow) * NB + n) * EDIM + h * HD + kck;
                cp16(&sKh[buf ^ 1][krow * PADK + kck], Khg + gk);
                cp16(&sKl[buf ^ 1][krow * PADK + kck], Klg + gk);
            }
            cp_commit();
            size_t gv = (size_t)((s1 + vkey) * NB + n) * EDIM + h * HD + vhd0;
            vh_cur = *(const uint2*)(Vhg + gv);
            vl_cur = *(const uint2*)(Vlg + gv);
        }

        // ---- S = Q @ K^T ----
        float4 s[4];
#pragma unroll
        for (int i = 0; i < 4; i++) s[i] = make_float4(0.f, 0.f, 0.f, 0.f);
#pragma unroll
        for (int ks = 0; ks < 2; ks++) {
            int kb = ks * 16 + 2 * t;
#pragma unroll
            for (int nt = 0; nt < 4; nt++) {
                int c = nt * 8 + g;    // key index
                unsigned bh0 = ldu(&sKh[buf][c * PADK + kb]);
                unsigned bh1 = ldu(&sKh[buf][c * PADK + kb + 8]);
                unsigned bl0 = ldu(&sKl[buf][c * PADK + kb]);
                unsigned bl1 = ldu(&sKl[buf][c * PADK + kb + 8]);
                mma_bf16(s[nt], qh[ks][0], qh[ks][1], qh[ks][2], qh[ks][3], bh0, bh1);
                mma_bf16(s[nt], qh[ks][0], qh[ks][1], qh[ks][2], qh[ks][3], bl0, bl1);
                mma_bf16(s[nt], ql[ks][0], ql[ks][1], ql[ks][2], ql[ks][3], bh0, bh1);
            }
        }
#pragma unroll
        for (int nt = 0; nt < 4; nt++) {
            s[nt].x *= scl2; s[nt].y *= scl2;
            s[nt].z *= scl2; s[nt].w *= scl2;
        }

        // ---- online softmax (base-2) ----
        float cm0 = fmaxf(fmaxf(s[0].x, s[0].y), fmaxf(s[1].x, s[1].y));
        cm0 = fmaxf(cm0, fmaxf(fmaxf(s[2].x, s[2].y), fmaxf(s[3].x, s[3].y)));
        float cm1 = fmaxf(fmaxf(s[0].z, s[0].w), fmaxf(s[1].z, s[1].w));
        cm1 = fmaxf(cm1, fmaxf(fmaxf(s[2].z, s[2].w), fmaxf(s[3].z, s[3].w)));
        cm0 = fmaxf(cm0, __shfl_xor_sync(0xffffffffu, cm0, 1));
        cm0 = fmaxf(cm0, __shfl_xor_sync(0xffffffffu, cm0, 2));
        cm1 = fmaxf(cm1, __shfl_xor_sync(0xffffffffu, cm1, 1));
        cm1 = fmaxf(cm1, __shfl_xor_sync(0xffffffffu, cm1, 2));

        float mn0 = fmaxf(m0, cm0);
        float mn1 = fmaxf(m1, cm1);
        float c0 = exp2f(m0 - mn0);
        float c1 = exp2f(m1 - mn1);

        float rs0 = 0.f, rs1 = 0.f;
#pragma unroll
        for (int nt = 0; nt < 4; nt++) {
            s[nt].x = exp2f(s[nt].x - mn0);
            s[nt].y = exp2f(s[nt].y - mn0);
            s[nt].z = exp2f(s[nt].z - mn1);
            s[nt].w = exp2f(s[nt].w - mn1);
            rs0 += s[nt].x + s[nt].y;
            rs1 += s[nt].z + s[nt].w;
        }
        rs0 += __shfl_xor_sync(0xffffffffu, rs0, 1);
        rs0 += __shfl_xor_sync(0xffffffffu, rs0, 2);
        rs1 += __shfl_xor_sync(0xffffffffu, rs1, 1);
        rs1 += __shfl_xor_sync(0xffffffffu, rs1, 2);

        l0 = l0 * c0 + rs0;
        l1 = l1 * c1 + rs1;
#pragma unroll
        for (int nt = 0; nt < 4; nt++) {
            o[nt].x *= c0; o[nt].y *= c0;
            o[nt].z *= c1; o[nt].w *= c1;
        }
        m0 = mn0; m1 = mn1;

        // P fragments: C-layout == A-layout (FA2), split hi/lo in registers
        __nv_bfloat162 hh, lll;
        unsigned ph[2][4], pl[2][4];
        split2(s[0].x, s[0].y, hh, lll); ph[0][0] = *(unsigned*)&hh; pl[0][0] = *(unsigned*)&lll;
        split2(s[0].z, s[0].w, hh, lll); ph[0][1] = *(unsigned*)&hh; pl[0][1] = *(unsigned*)&lll;
        split2(s[1].x, s[1].y, hh, lll); ph[0][2] = *(unsigned*)&hh; pl[0][2] = *(unsigned*)&lll;
        split2(s[1].z, s[1].w, hh, lll); ph[0][3] = *(unsigned*)&hh; pl[0][3] = *(unsigned*)&lll;
        split2(s[2].x, s[2].y, hh, lll); ph[1][0] = *(unsigned*)&hh; pl[1][0] = *(unsigned*)&lll;
        split2(s[2].z, s[2].w, hh, lll); ph[1][1] = *(unsigned*)&hh; pl[1][1] = *(unsigned*)&lll;
        split2(s[3].x, s[3].y, hh, lll); ph[1][2] = *(unsigned*)&hh; pl[1][2] = *(unsigned*)&lll;
        split2(s[3].z, s[3].w, hh, lll); ph[1][3] = *(unsigned*)&hh; pl[1][3] = *(unsigned*)&lll;

        // ---- O += P @ V ----
#pragma unroll
        for (int ks = 0; ks < 2; ks++) {
            int kb = ks * 16 + 2 * t;  // key offset
#pragma unroll
            for (int nt = 0; nt < 4; nt++) {
                int c = nt * 8 + g;    // hd index
                unsigned bh0 = ldu(&sVh[buf][c * PADK + kb]);
                unsigned bh1 = ldu(&sVh[buf][c * PADK + kb + 8]);
                unsigned bl0 = ldu(&sVl[buf][c * PADK + kb]);
                unsigned bl1 = ldu(&sVl[buf][c * PADK + kb + 8]);
                mma_bf16(o[nt], ph[ks][0], ph[ks][1], ph[ks][2], ph[ks][3], bh0, bh1);
                mma_bf16(o[nt], ph[ks][0], ph[ks][1], ph[ks][2], ph[ks][3], bl0, bl1);
                mma_bf16(o[nt], pl[ks][0], pl[ks][1], pl[ks][2], pl[ks][3], bh0, bh1);
            }
        }
        __syncthreads();   // retire this chunk's readers before next V STS / K cp
    }

    const float inv0 = 1.f / l0;
    const float inv1 = 1.f / l1;
    const int lrow = qbase + ar + g;
    const size_t base0 = (size_t)(lrow * NB + n) * EDIM + h * HD;
    const size_t base1 = (size_t)((lrow + 8) * NB + n) * EDIM + h * HD;
#pragma unroll
    for (int nt = 0; nt < 4; nt++) {
        int col = nt * 8 + 2 * t;
        __nv_bfloat162 h0, l0b, h1, l1b;
        split2(o[nt].x * inv0, o[nt].y * inv0, h0, l0b);
        split2(o[nt].z * inv1, o[nt].w * inv1, h1, l1b);
        *(__nv_bfloat162*)&Oh[base0 + col] = h0;
        *(__nv_bfloat162*)&Ol[base0 + col] = l0b;
        *(__nv_bfloat162*)&Oh[base1 + col] = h1;
        *(__nv_bfloat162*)&Ol[base1 + col] = l1b;
    }
}

// ---------------------------------------------------------------------------
// Input order = setup_inputs() dict order:
//  0 query, 1 key, 2 value, 3 query_teacher, 4 key_teacher, 5 value_teacher,
//  6 w_q, 7 w_k, 8 w_v, 9 w_q_teacher, 10 w_k_teacher, 11 w_v_teacher,
//  12 w_out, 13 w_out_teacher,
//  14 b_q, 15 b_k, 16 b_v, 17 b_q_teacher, 18 b_k_teacher, 19 b_v_teacher,
//  20 b_out, 21 b_out_teacher
// ---------------------------------------------------------------------------
extern "C" void kernel_launch(void* const* d_in, const int* in_sizes, int n_in,
                              void* d_out, int out_size)
{
    const float* P[22];
    for (int i = 0; i < 22; i++) P[i] = (const float*)d_in[i];

    // pre-split fp32 -> bf16 hi/lo
    dim3 gsa(TOK * EDIM / (4 * 256), 1, 6);
    split_act_kernel<<<gsa, 256>>>(P[0], P[1], P[2], P[3], P[4], P[5]);
    dim3 gsw(EDIM * EDIM / (4 * 256), 1, 8);
    split_w_kernel<<<gsw, 256>>>(P[6], P[7], P[8], P[9], P[10], P[11],
                                 P[12], P[13]);

    dim3 gin(2, 64, 6);
    inproj_kernel<<<gin, 256>>>(P[14], P[15], P[16], P[17], P[18], P[19]);

    dim3 gat(8, 128);               // 8 q-blocks x (2 streams * 8 n * 8 h)
    attn_kernel<<<gat, 256>>>();

    dim3 gout(2, 64, 2);
    outproj_kernel<<<gout, 256>>>(P[20], P[21], (float*)d_out);
}

// round 16
// speedup vs baseline: 2.8454x; 1.0889x over previous
#include <cuda_runtime.h>
#include <cuda_bf16.h>
#include <cuda_fp16.h>

#define TOK   8192   // L*N tokens
#define EDIM  256
#define HD    32
#define NB    8      // batch N
#define LQ    1024   // seq len
#define PADK  40     // bf16 elements per smem row (80B stride: 16B-aligned, conflict-free)

// softmax scale folded into Q at projection: (1/sqrt(32)) * log2(e)
#define QSCALE 0.25503262673998393f

// bf16 hi/lo planes: activations, weights, Q/K proj outputs, attention outputs
__device__ __nv_bfloat16 g_xh[6][TOK * EDIM], g_xl[6][TOK * EDIM];
__device__ __nv_bfloat16 g_wh[8][EDIM * EDIM], g_wl[8][EDIM * EDIM];
__device__ __nv_bfloat16 g_ph[6][TOK * EDIM], g_pl[6][TOK * EDIM];
__device__ __nv_bfloat16 g_oh[2][TOK * EDIM], g_ol[2][TOK * EDIM];
// V projection in fp16 hi/lo planes (PV runs fp16)
__device__ __half g_vh[2][TOK * EDIM], g_vl[2][TOK * EDIM];

// ---------------------------------------------------------------------------
// helpers
// ---------------------------------------------------------------------------
__device__ __forceinline__ void mma_bf16(float4& d,
    unsigned a0, unsigned a1, unsigned a2, unsigned a3,
    unsigned b0, unsigned b1)
{
    asm volatile(
        "mma.sync.aligned.m16n8k16.row.col.f32.bf16.bf16.f32 "
        "{%0,%1,%2,%3}, {%4,%5,%6,%7}, {%8,%9}, {%0,%1,%2,%3};"
        : "+f"(d.x), "+f"(d.y), "+f"(d.z), "+f"(d.w)
        : "r"(a0), "r"(a1), "r"(a2), "r"(a3), "r"(b0), "r"(b1));
}

__device__ __forceinline__ void mma_f16(float4& d,
    unsigned a0, unsigned a1, unsigned a2, unsigned a3,
    unsigned b0, unsigned b1)
{
    asm volatile(
        "mma.sync.aligned.m16n8k16.row.col.f32.f16.f16.f32 "
        "{%0,%1,%2,%3}, {%4,%5,%6,%7}, {%8,%9}, {%0,%1,%2,%3};"
        : "+f"(d.x), "+f"(d.y), "+f"(d.z), "+f"(d.w)
        : "r"(a0), "r"(a1), "r"(a2), "r"(a3), "r"(b0), "r"(b1));
}

__device__ __forceinline__ void ldsm4(unsigned& r0, unsigned& r1,
                                      unsigned& r2, unsigned& r3, unsigned addr)
{
    asm volatile("ldmatrix.sync.aligned.m8n8.x4.shared.b16 {%0,%1,%2,%3}, [%4];"
        : "=r"(r0), "=r"(r1), "=r"(r2), "=r"(r3) : "r"(addr));
}

__device__ __forceinline__ void cp16(void* smem, const void* gmem)
{
    unsigned s = (unsigned)__cvta_generic_to_shared(smem);
    asm volatile("cp.async.ca.shared.global [%0], [%1], 16;" :: "r"(s), "l"(gmem));
}
__device__ __forceinline__ void cp_commit()
{
    asm volatile("cp.async.commit_group;");
}
__device__ __forceinline__ void cp_wait0()
{
    asm volatile("cp.async.wait_group 0;" ::: "memory");
}

__device__ __forceinline__ unsigned ldu(const __nv_bfloat16* p)
{
    return *reinterpret_cast<const unsigned*>(p);
}

// split two floats into packed bf16x2 hi + residual lo
__device__ __forceinline__ void split2(float x, float y,
    __nv_bfloat162& h, __nv_bfloat162& l)
{
    h = __floats2bfloat162_rn(x, y);
    float2 f = __bfloat1622float2(h);
    l = __floats2bfloat162_rn(x - f.x, y - f.y);
}

// ---------------------------------------------------------------------------
// pre-split kernels: fp32 -> bf16 hi/lo planes
// ---------------------------------------------------------------------------
__global__ __launch_bounds__(256) void split_act_kernel(
    const float* a0, const float* a1, const float* a2,
    const float* a3, const float* a4, const float* a5)
{
    const float* src[6] = {a0, a1, a2, a3, a4, a5};
    const int z = blockIdx.z;
    const int i = (blockIdx.x * 256 + threadIdx.x) * 4;
    float4 v = *(const float4*)&src[z][i];
    __nv_bfloat162 h01, l01, h23, l23;
    split2(v.x, v.y, h01, l01);
    split2(v.z, v.w, h23, l23);
    *(__nv_bfloat162*)&g_xh[z][i]     = h01;
    *(__nv_bfloat162*)&g_xh[z][i + 2] = h23;
    *(__nv_bfloat162*)&g_xl[z][i]     = l01;
    *(__nv_bfloat162*)&g_xl[z][i + 2] = l23;
}

__global__ __launch_bounds__(256) void split_w_kernel(
    const float* w0, const float* w1, const float* w2, const float* w3,
    const float* w4, const float* w5, const float* w6, const float* w7)
{
    const float* src[8] = {w0, w1, w2, w3, w4, w5, w6, w7};
    const int z = blockIdx.z;
    const int i = (blockIdx.x * 256 + threadIdx.x) * 4;
    float4 v = *(const float4*)&src[z][i];
    __nv_bfloat162 h01, l01, h23, l23;
    split2(v.x, v.y, h01, l01);
    split2(v.z, v.w, h23, l23);
    *(__nv_bfloat162*)&g_wh[z][i]     = h01;
    *(__nv_bfloat162*)&g_wh[z][i + 2] = h23;
    *(__nv_bfloat162*)&g_wl[z][i]     = l01;
    *(__nv_bfloat162*)&g_wl[z][i + 2] = l23;
}

// ---------------------------------------------------------------------------
// GEMM core: C[M,256] = oscale*(X @ W^T + bias), bf16x3 split MMA.
// Output: fp32 (Cf), bf16 hi/lo (Ch/Cl), or fp16 hi/lo (Hh/Hl).
// ---------------------------------------------------------------------------
__device__ __forceinline__ void gemm_core(
    const __nv_bfloat16* __restrict__ Xh, const __nv_bfloat16* __restrict__ Xl,
    const __nv_bfloat16* __restrict__ Wh, const __nv_bfloat16* __restrict__ Wl,
    const float* __restrict__ bias,
    __nv_bfloat16* __restrict__ Ch, __nv_bfloat16* __restrict__ Cl,
    float* __restrict__ Cf,
    __half* __restrict__ Hh, __half* __restrict__ Hl,
    float oscale)
{
    __shared__ __nv_bfloat16 sXh[128 * PADK], sXl[128 * PADK];
    __shared__ __nv_bfloat16 sWh[128 * PADK], sWl[128 * PADK];

    const int tid  = threadIdx.x;
    const int wid  = tid >> 5;
    const int lane = tid & 31;
    const int g = lane >> 2, t = lane & 3;
    const int wm = (wid >> 1) * 32;
    const int wn = (wid & 1) * 64;
    const int m0 = blockIdx.y * 128;
    const int n0 = blockIdx.x * 128;

    float4 acc[2][8];
#pragma unroll
    for (int i = 0; i < 2; i++)
#pragma unroll
        for (int j = 0; j < 8; j++) acc[i][j] = make_float4(0.f, 0.f, 0.f, 0.f);

    for (int k0 = 0; k0 < EDIM; k0 += 32) {
#pragma unroll
        for (int i = 0; i < 2; i++) {
            int id  = tid + i * 256;
            int row = id >> 2;
            int ck  = (id & 3) * 8;
            size_t gx = (size_t)(m0 + row) * EDIM + k0 + ck;
            size_t gw = (size_t)(n0 + row) * EDIM + k0 + ck;
            cp16(&sXh[row * PADK + ck], Xh + gx);
            cp16(&sXl[row * PADK + ck], Xl + gx);
            cp16(&sWh[row * PADK + ck], Wh + gw);
            cp16(&sWl[row * PADK + ck], Wl + gw);
        }
        cp_commit();
        cp_wait0();
        __syncthreads();

#pragma unroll
        for (int ks = 0; ks < 2; ks++) {
            const int kb = ks * 16 + 2 * t;
            unsigned ah[2][4], al[2][4];
#pragma unroll
            for (int mt = 0; mt < 2; mt++) {
                int r = wm + mt * 16 + g;
                ah[mt][0] = ldu(&sXh[r * PADK + kb]);
                ah[mt][1] = ldu(&sXh[(r + 8) * PADK + kb]);
                ah[mt][2] = ldu(&sXh[r * PADK + kb + 8]);
                ah[mt][3] = ldu(&sXh[(r + 8) * PADK + kb + 8]);
                al[mt][0] = ldu(&sXl[r * PADK + kb]);
                al[mt][1] = ldu(&sXl[(r + 8) * PADK + kb]);
                al[mt][2] = ldu(&sXl[r * PADK + kb + 8]);
                al[mt][3] = ldu(&sXl[(r + 8) * PADK + kb + 8]);
            }
#pragma unroll
            for (int nt = 0; nt < 8; nt++) {
                int c = wn + nt * 8 + g;
                unsigned bh0 = ldu(&sWh[c * PADK + kb]);
                unsigned bh1 = ldu(&sWh[c * PADK + kb + 8]);
                unsigned bl0 = ldu(&sWl[c * PADK + kb]);
                unsigned bl1 = ldu(&sWl[c * PADK + kb + 8]);
#pragma unroll
                for (int mt = 0; mt < 2; mt++) {
                    mma_bf16(acc[mt][nt], ah[mt][0], ah[mt][1], ah[mt][2], ah[mt][3], bh0, bh1);
                    mma_bf16(acc[mt][nt], ah[mt][0], ah[mt][1], ah[mt][2], ah[mt][3], bl0, bl1);
                    mma_bf16(acc[mt][nt], al[mt][0], al[mt][1], al[mt][2], al[mt][3], bh0, bh1);
                }
            }
        }
        __syncthreads();
    }

#pragma unroll
    for (int mt = 0; mt < 2; mt++)
#pragma unroll
        for (int nt = 0; nt < 8; nt++) {
            int row = m0 + wm + mt * 16 + g;
            int col = n0 + wn + nt * 8 + 2 * t;
            float2 bb = *(const float2*)&bias[col];
            float4 a = acc[mt][nt];
            float v0x = (a.x + bb.x) * oscale, v0y = (a.y + bb.y) * oscale;
            float v1x = (a.z + bb.x) * oscale, v1y = (a.w + bb.y) * oscale;
            size_t o0 = (size_t)row * EDIM + col;
            size_t o1 = (size_t)(row + 8) * EDIM + col;
            if (Cf) {
                *(float2*)&Cf[o0] = make_float2(v0x, v0y);
                *(float2*)&Cf[o1] = make_float2(v1x, v1y);
            } else if (Hh) {
                __half2 h0 = __float22half2_rn(make_float2(v0x, v0y));
                float2 f0 = __half22float2(h0);
                __half2 e0 = __float22half2_rn(make_float2(v0x - f0.x, v0y - f0.y));
                __half2 h1 = __float22half2_rn(make_float2(v1x, v1y));
                float2 f1 = __half22float2(h1);
                __half2 e1 = __float22half2_rn(make_float2(v1x - f1.x, v1y - f1.y));
                *(__half2*)&Hh[o0] = h0; *(__half2*)&Hl[o0] = e0;
                *(__half2*)&Hh[o1] = h1; *(__half2*)&Hl[o1] = e1;
            } else {
                __nv_bfloat162 h0, l0, h1, l1;
                split2(v0x, v0y, h0, l0);
                split2(v1x, v1y, h1, l1);
                *(__nv_bfloat162*)&Ch[o0] = h0; *(__nv_bfloat162*)&Cl[o0] = l0;
                *(__nv_bfloat162*)&Ch[o1] = h1; *(__nv_bfloat162*)&Cl[o1] = l1;
            }
        }
}

__global__ __launch_bounds__(256, 2) void inproj_kernel(
    const float* b0, const float* b1, const float* b2,
    const float* b3, const float* b4, const float* b5)
{
    const float* Bs[6] = {b0, b1, b2, b3, b4, b5};
    const int z = blockIdx.z;
    const int s = z / 3, r = z % 3;
    if (r == 2) {
        // V stream -> fp16 planes
        gemm_core(g_xh[z], g_xl[z], g_wh[z], g_wl[z], Bs[z],
                  nullptr, nullptr, nullptr, g_vh[s], g_vl[s], 1.0f);
    } else {
        // Q stream carries folded softmax scale; K unscaled
        float os = (r == 0) ? QSCALE : 1.0f;
        gemm_core(g_xh[z], g_xl[z], g_wh[z], g_wl[z], Bs[z],
                  g_ph[z], g_pl[z], nullptr, nullptr, nullptr, os);
    }
}

__global__ __launch_bounds__(256, 2) void outproj_kernel(
    const float* bo, const float* bot, float* out)
{
    const int z = blockIdx.z;
    gemm_core(g_oh[z], g_ol[z], g_wh[6 + z], g_wl[6 + z], z ? bot : bo,
              nullptr, nullptr, out + (size_t)z * TOK * EDIM,
              nullptr, nullptr, 1.0f);
}

// ---------------------------------------------------------------------------
// Flash attention: QK bf16x3 (ldmatrix frags), softmax exp2 (scale pre-folded
// into Q), P fp16 single, PV fp16x2. Double-buffered K/V, 1 barrier/chunk.
// ---------------------------------------------------------------------------
__global__ __launch_bounds__(256, 2) void attn_kernel()
{
    __shared__ __nv_bfloat16 sQh[128 * PADK], sQl[128 * PADK];
    __shared__ __nv_bfloat16 sKh[2][32 * PADK], sKl[2][32 * PADK];
    __shared__ __half        sVh[2][32 * PADK], sVl[2][32 * PADK]; // [hd][key]

    const int tid  = threadIdx.x;
    const int wid  = tid >> 5;
    const int lane = tid & 31;
    const int g = lane >> 2, t = lane & 3;

    const int idx    = blockIdx.y;
    const int stream = idx >> 6;
    const int n      = (idx >> 3) & 7;
    const int h      = idx & 7;

    const __nv_bfloat16* __restrict__ Qhg = g_ph[stream * 3 + 0];
    const __nv_bfloat16* __restrict__ Qlg = g_pl[stream * 3 + 0];
    const __nv_bfloat16* __restrict__ Khg = g_ph[stream * 3 + 1];
    const __nv_bfloat16* __restrict__ Klg = g_pl[stream * 3 + 1];
    const __half* __restrict__ Vhg = g_vh[stream];
    const __half* __restrict__ Vlg = g_vl[stream];
    __nv_bfloat16* __restrict__ Oh = g_oh[stream];
    __nv_bfloat16* __restrict__ Ol = g_ol[stream];

    const int qbase = blockIdx.x * 128;

    // K staging coords (threads 0..127): row=key, ck=bf16 col
    const int krow = tid >> 2;
    const int kck  = (tid & 3) * 8;
    // V staging coords (all 256): key, hd quad
    const int vkey = tid >> 3;
    const int vhd0 = (tid & 7) * 4;

    // ldmatrix per-thread byte offset: tile row + k-half column
    const int lrow8 = ((lane >> 4) * 8 + (lane & 7));
    const unsigned lmoff = (unsigned)((lrow8 * PADK + ((lane >> 3) & 1) * 8) * 2);

    const unsigned aKh0 = (unsigned)__cvta_generic_to_shared(&sKh[0][0]) + lmoff;
    const unsigned aKh1 = (unsigned)__cvta_generic_to_shared(&sKh[1][0]) + lmoff;
    const unsigned aKl0 = (unsigned)__cvta_generic_to_shared(&sKl[0][0]) + lmoff;
    const unsigned aKl1 = (unsigned)__cvta_generic_to_shared(&sKl[1][0]) + lmoff;
    const unsigned aVh0 = (unsigned)__cvta_generic_to_shared(&sVh[0][0]) + lmoff;
    const unsigned aVh1 = (unsigned)__cvta_generic_to_shared(&sVh[1][0]) + lmoff;
    const unsigned aVl0 = (unsigned)__cvta_generic_to_shared(&sVl[0][0]) + lmoff;
    const unsigned aVl1 = (unsigned)__cvta_generic_to_shared(&sVl[1][0]) + lmoff;
    const unsigned ROW16 = 16u * PADK * 2u;   // +16 rows (keys or hd)
    const unsigned COL16 = 32u;               // +16 bf16/fp16 columns

    // ---- prologue: stage Q + K chunk 0, load V chunk 0 regs ----
#pragma unroll
    for (int i = 0; i < 2; i++) {
        int id  = tid + i * 256;
        int row = id >> 2;
        int ck  = (id & 3) * 8;
        size_t gq = (size_t)((qbase + row) * NB + n) * EDIM + h * HD + ck;
        cp16(&sQh[row * PADK + ck], Qhg + gq);
        cp16(&sQl[row * PADK + ck], Qlg + gq);
    }
    if (tid < 128) {
        size_t gk = (size_t)(krow * NB + n) * EDIM + h * HD + kck;
        cp16(&sKh[0][krow * PADK + kck], Khg + gk);
        cp16(&sKl[0][krow * PADK + kck], Klg + gk);
    }
    cp_commit();
    uint2 vh_cur, vl_cur;
    {
        size_t gv = (size_t)(vkey * NB + n) * EDIM + h * HD + vhd0;
        vh_cur = *(const uint2*)(Vhg + gv);
        vl_cur = *(const uint2*)(Vlg + gv);
    }
    cp_wait0();
    __syncthreads();

    // per-warp persistent Q fragments: 2 k-steps of k16
    unsigned qh[2][4], ql[2][4];
    const int ar = wid * 16;
#pragma unroll
    for (int ks = 0; ks < 2; ks++) {
        int kb = ks * 16 + 2 * t;
        qh[ks][0] = ldu(&sQh[(ar + g) * PADK + kb]);
        qh[ks][1] = ldu(&sQh[(ar + g + 8) * PADK + kb]);
        qh[ks][2] = ldu(&sQh[(ar + g) * PADK + kb + 8]);
        qh[ks][3] = ldu(&sQh[(ar + g + 8) * PADK + kb + 8]);
        ql[ks][0] = ldu(&sQl[(ar + g) * PADK + kb]);
        ql[ks][1] = ldu(&sQl[(ar + g + 8) * PADK + kb]);
        ql[ks][2] = ldu(&sQl[(ar + g) * PADK + kb + 8]);
        ql[ks][3] = ldu(&sQl[(ar + g + 8) * PADK + kb + 8]);
    }

    float4 o[4];
#pragma unroll
    for (int i = 0; i < 4; i++) o[i] = make_float4(0.f, 0.f, 0.f, 0.f);
    float m0 = -1e30f, m1 = -1e30f, l0 = 0.f, l1 = 0.f;

    for (int ci = 0; ci < 32; ci++) {
        const int buf = ci & 1;
        if (ci) cp_wait0();           // K(ci) landed (issued last iteration)

        // V(ci) transpose store from regs (loaded last iteration / prologue)
        {
            __half eh[4], el[4];
            *(uint2*)eh = vh_cur; *(uint2*)el = vl_cur;
#pragma unroll
            for (int j = 0; j < 4; j++) {
                sVh[buf][(vhd0 + j) * PADK + vkey] = eh[j];
                sVl[buf][(vhd0 + j) * PADK + vkey] = el[j];
            }
        }
        __syncthreads();   // K(ci)+V(ci) visible; compute(ci-1) readers retired

        // prefetch chunk ci+1 (overlaps with compute below)
        if (ci + 1 < 32) {
            const int s1 = (ci + 1) * 32;
            if (tid < 128) {
                size_t gk = (size_t)((s1 + krow) * NB + n) * EDIM + h * HD + kck;
                cp16(&sKh[buf ^ 1][krow * PADK + kck], Khg + gk);
                cp16(&sKl[buf ^ 1][krow * PADK + kck], Klg + gk);
            }
            cp_commit();
            size_t gv = (size_t)((s1 + vkey) * NB + n) * EDIM + h * HD + vhd0;
            vh_cur = *(const uint2*)(Vhg + gv);
            vl_cur = *(const uint2*)(Vlg + gv);
        }

        const unsigned aKh = buf ? aKh1 : aKh0;
        const unsigned aKl = buf ? aKl1 : aKl0;
        const unsigned aVh = buf ? aVh1 : aVh0;
        const unsigned aVl = buf ? aVl1 : aVl0;

        // ---- S = Q @ K^T (scores arrive pre-scaled into exp2 domain) ----
        float4 s[4];
#pragma unroll
        for (int i = 0; i < 4; i++) s[i] = make_float4(0.f, 0.f, 0.f, 0.f);
#pragma unroll
        for (int ks = 0; ks < 2; ks++) {
            unsigned kh0[4], kh1[4], kl0[4], kl1[4];
            ldsm4(kh0[0], kh1[0], kh0[1], kh1[1], aKh + ks * COL16);
            ldsm4(kh0[2], kh1[2], kh0[3], kh1[3], aKh + ks * COL16 + ROW16);
            ldsm4(kl0[0], kl1[0], kl0[1], kl1[1], aKl + ks * COL16);
            ldsm4(kl0[2], kl1[2], kl0[3], kl1[3], aKl + ks * COL16 + ROW16);
#pragma unroll
            for (int nt = 0; nt < 4; nt++) {
                mma_bf16(s[nt], qh[ks][0], qh[ks][1], qh[ks][2], qh[ks][3], kh0[nt], kh1[nt]);
                mma_bf16(s[nt], qh[ks][0], qh[ks][1], qh[ks][2], qh[ks][3], kl0[nt], kl1[nt]);
                mma_bf16(s[nt], ql[ks][0], ql[ks][1], ql[ks][2], ql[ks][3], kh0[nt], kh1[nt]);
            }
        }

        // ---- online softmax (base-2 domain) ----
        float cm0 = fmaxf(fmaxf(s[0].x, s[0].y), fmaxf(s[1].x, s[1].y));
        cm0 = fmaxf(cm0, fmaxf(fmaxf(s[2].x, s[2].y), fmaxf(s[3].x, s[3].y)));
        float cm1 = fmaxf(fmaxf(s[0].z, s[0].w), fmaxf(s[1].z, s[1].w));
        cm1 = fmaxf(cm1, fmaxf(fmaxf(s[2].z, s[2].w), fmaxf(s[3].z, s[3].w)));
        cm0 = fmaxf(cm0, __shfl_xor_sync(0xffffffffu, cm0, 1));
        cm0 = fmaxf(cm0, __shfl_xor_sync(0xffffffffu, cm0, 2));
        cm1 = fmaxf(cm1, __shfl_xor_sync(0xffffffffu, cm1, 1));
        cm1 = fmaxf(cm1, __shfl_xor_sync(0xffffffffu, cm1, 2));

        float mn0 = fmaxf(m0, cm0);
        float mn1 = fmaxf(m1, cm1);
        float c0 = exp2f(m0 - mn0);
        float c1 = exp2f(m1 - mn1);

        float rs0 = 0.f, rs1 = 0.f;
#pragma unroll
        for (int nt = 0; nt < 4; nt++) {
            s[nt].x = exp2f(s[nt].x - mn0);
            s[nt].y = exp2f(s[nt].y - mn0);
            s[nt].z = exp2f(s[nt].z - mn1);
            s[nt].w = exp2f(s[nt].w - mn1);
            rs0 += s[nt].x + s[nt].y;
            rs1 += s[nt].z + s[nt].w;
        }
        rs0 += __shfl_xor_sync(0xffffffffu, rs0, 1);
        rs0 += __shfl_xor_sync(0xffffffffu, rs0, 2);
        rs1 += __shfl_xor_sync(0xffffffffu, rs1, 1);
        rs1 += __shfl_xor_sync(0xffffffffu, rs1, 2);

        l0 = l0 * c0 + rs0;
        l1 = l1 * c1 + rs1;
#pragma unroll
        for (int nt = 0; nt < 4; nt++) {
            o[nt].x *= c0; o[nt].y *= c0;
            o[nt].z *= c1; o[nt].w *= c1;
        }
        m0 = mn0; m1 = mn1;

        // P fragments: C-layout == A-layout (FA2), single fp16
        unsigned ph[2][4];
        {
            __half2 p;
            p = __float22half2_rn(make_float2(s[0].x, s[0].y)); ph[0][0] = *(unsigned*)&p;
            p = __float22half2_rn(make_float2(s[0].z, s[0].w)); ph[0][1] = *(unsigned*)&p;
            p = __float22half2_rn(make_float2(s[1].x, s[1].y)); ph[0][2] = *(unsigned*)&p;
            p = __float22half2_rn(make_float2(s[1].z, s[1].w)); ph[0][3] = *(unsigned*)&p;
            p = __float22half2_rn(make_float2(s[2].x, s[2].y)); ph[1][0] = *(unsigned*)&p;
            p = __float22half2_rn(make_float2(s[2].z, s[2].w)); ph[1][1] = *(unsigned*)&p;
            p = __float22half2_rn(make_float2(s[3].x, s[3].y)); ph[1][2] = *(unsigned*)&p;
            p = __float22half2_rn(make_float2(s[3].z, s[3].w)); ph[1][3] = *(unsigned*)&p;
        }

        // ---- O += P @ V (fp16: p·Vh + p·Vl) ----
#pragma unroll
        for (int ks = 0; ks < 2; ks++) {
            unsigned vh0[4], vh1[4], vl0[4], vl1[4];
            ldsm4(vh0[0], vh1[0], vh0[1], vh1[1], aVh + ks * COL16);
            ldsm4(vh0[2], vh1[2], vh0[3], vh1[3], aVh + ks * COL16 + ROW16);
            ldsm4(vl0[0], vl1[0], vl0[1], vl1[1], aVl + ks * COL16);
            ldsm4(vl0[2], vl1[2], vl0[3], vl1[3], aVl + ks * COL16 + ROW16);
#pragma unroll
            for (int nt = 0; nt < 4; nt++) {
                mma_f16(o[nt], ph[ks][0], ph[ks][1], ph[ks][2], ph[ks][3], vh0[nt], vh1[nt]);
                mma_f16(o[nt], ph[ks][0], ph[ks][1], ph[ks][2], ph[ks][3], vl0[nt], vl1[nt]);
            }
        }
        __syncthreads();   // retire this chunk's readers before next V STS / K cp
    }

    const float inv0 = 1.f / l0;
    const float inv1 = 1.f / l1;
    const int lrow = qbase + ar + g;
    const size_t base0 = (size_t)(lrow * NB + n) * EDIM + h * HD;
    const size_t base1 = (size_t)((lrow + 8) * NB + n) * EDIM + h * HD;
#pragma unroll
    for (int nt = 0; nt < 4; nt++) {
        int col = nt * 8 + 2 * t;
        __nv_bfloat162 h0, l0b, h1, l1b;
        split2(o[nt].x * inv0, o[nt].y * inv0, h0, l0b);
        split2(o[nt].z * inv1, o[nt].w * inv1, h1, l1b);
        *(__nv_bfloat162*)&Oh[base0 + col] = h0;
        *(__nv_bfloat162*)&Ol[base0 + col] = l0b;
        *(__nv_bfloat162*)&Oh[base1 + col] = h1;
        *(__nv_bfloat162*)&Ol[base1 + col] = l1b;
    }
}

// ---------------------------------------------------------------------------
// Input order = setup_inputs() dict order:
//  0 query, 1 key, 2 value, 3 query_teacher, 4 key_teacher, 5 value_teacher,
//  6 w_q, 7 w_k, 8 w_v, 9 w_q_teacher, 10 w_k_teacher, 11 w_v_teacher,
//  12 w_out, 13 w_out_teacher,
//  14 b_q, 15 b_k, 16 b_v, 17 b_q_teacher, 18 b_k_teacher, 19 b_v_teacher,
//  20 b_out, 21 b_out_teacher
// ---------------------------------------------------------------------------
extern "C" void kernel_launch(void* const* d_in, const int* in_sizes, int n_in,
                              void* d_out, int out_size)
{
    const float* P[22];
    for (int i = 0; i < 22; i++) P[i] = (const float*)d_in[i];

    // pre-split fp32 -> bf16 hi/lo
    dim3 gsa(TOK * EDIM / (4 * 256), 1, 6);
    split_act_kernel<<<gsa, 256>>>(P[0], P[1], P[2], P[3], P[4], P[5]);
    dim3 gsw(EDIM * EDIM / (4 * 256), 1, 8);
    split_w_kernel<<<gsw, 256>>>(P[6], P[7], P[8], P[9], P[10], P[11],
                                 P[12], P[13]);

    dim3 gin(2, 64, 6);
    inproj_kernel<<<gin, 256>>>(P[14], P[15], P[16], P[17], P[18], P[19]);

    dim3 gat(8, 128);               // 8 q-blocks x (2 streams * 8 n * 8 h)
    attn_kernel<<<gat, 256>>>();

    dim3 gout(2, 64, 2);
    outproj_kernel<<<gout, 256>>>(P[20], P[21], (float*)d_out);
}